// round 14
// baseline (speedup 1.0000x reference)
#include <cuda_runtime.h>
#include <cuda_fp16.h>
#include <stdint.h>
#include <math.h>

#define H_SIZE 2048
#define INTER_SZ 8192
#define NQ 16
#define NKV 8
#define HD 128
#define SEQ 2048
#define BATCH 2
#define NROWS (BATCH*SEQ)
#define WIN 1024

// ---------------- fp32 scratch ----------------
__device__ float g_q[NROWS*H_SIZE];
__device__ float g_k[NROWS*NKV*HD];
__device__ float g_v[NROWS*NKV*HD];
__device__ float g_attnout[NROWS*H_SIZE];
__device__ float g_h2[NROWS*H_SIZE];
__device__ float g_gate[NROWS*INTER_SZ];
__device__ float g_up[NROWS*INTER_SZ];
__device__ float g_ffnout[NROWS*H_SIZE];

// ---------------- fp16 planes ----------------
__device__ __half g_h_h[NROWS*H_SIZE],      g_h_l[NROWS*H_SIZE];
__device__ __half g_attn_h[NROWS*H_SIZE],   g_attn_l[NROWS*H_SIZE];
__device__ __half g_ffnin_h[NROWS*H_SIZE],  g_ffnin_l[NROWS*H_SIZE];
__device__ __half g_gact_h[NROWS*INTER_SZ];
__device__ __half g_wq[H_SIZE*H_SIZE];
__device__ __half g_wk[NKV*HD*H_SIZE];
__device__ __half g_wv[NKV*HD*H_SIZE];
__device__ __half g_wo[H_SIZE*H_SIZE];
__device__ __half g_wg[INTER_SZ*H_SIZE];
__device__ __half g_wu[INTER_SZ*H_SIZE];
__device__ __half g_wd[H_SIZE*INTER_SZ];

// ---------------- helpers ----------------
__device__ __forceinline__ void split2h(float a, float b, __half* hi, __half* lo) {
    __half ha = __float2half(a), hb = __float2half(b);
    __half la = __float2half(a - __half2float(ha));
    __half lb = __float2half(b - __half2float(hb));
    *(__half2*)hi = __halves2half2(ha, hb);
    *(__half2*)lo = __halves2half2(la, lb);
}

__global__ __launch_bounds__(256) void wsplit_kernel(
    const float* __restrict__ in, __half* __restrict__ out, int n4)
{
    int i = blockIdx.x * blockDim.x + threadIdx.x;
    int stride = gridDim.x * blockDim.x;
    for (; i < n4; i += stride) {
        float4 v = ((const float4*)in)[i];
        *(__half2*)(out + i*4)     = __halves2half2(__float2half(v.x), __float2half(v.y));
        *(__half2*)(out + i*4 + 2) = __halves2half2(__float2half(v.z), __float2half(v.w));
    }
}

// ---------------- RMSNorm fp32 out ----------------
__global__ __launch_bounds__(256) void rmsnorm_kernel(
    const float* __restrict__ in, const float* __restrict__ w,
    const float* __restrict__ res, const float* __restrict__ scal,
    float* __restrict__ out, int mode)
{
    int row = blockIdx.x;
    int t = threadIdx.x;
    const float4* ip = (const float4*)(in + (size_t)row * H_SIZE);
    float4 v0 = ip[t];
    float4 v1 = ip[t + 256];
    float ss = v0.x*v0.x + v0.y*v0.y + v0.z*v0.z + v0.w*v0.w
             + v1.x*v1.x + v1.y*v1.y + v1.z*v1.z + v1.w*v1.w;
    #pragma unroll
    for (int o = 16; o; o >>= 1) ss += __shfl_xor_sync(0xffffffffu, ss, o);
    __shared__ float red[8];
    if ((t & 31) == 0) red[t >> 5] = ss;
    __syncthreads();
    float tot = red[0]+red[1]+red[2]+red[3]+red[4]+red[5]+red[6]+red[7];
    float inv = rsqrtf(tot * (1.0f / H_SIZE) + 1e-6f);

    const float4* w4 = (const float4*)w;
    float4 w0 = w4[t], w1 = w4[t + 256];
    float4 o0, o1;
    o0.x = v0.x*inv*w0.x; o0.y = v0.y*inv*w0.y; o0.z = v0.z*inv*w0.z; o0.w = v0.w*inv*w0.w;
    o1.x = v1.x*inv*w1.x; o1.y = v1.y*inv*w1.y; o1.z = v1.z*inv*w1.z; o1.w = v1.w*inv*w1.w;
    if (mode >= 1) {
        const float4* rp = (const float4*)(res + (size_t)row * H_SIZE);
        float4 r0 = rp[t], r1 = rp[t + 256];
        o0.x += r0.x; o0.y += r0.y; o0.z += r0.z; o0.w += r0.w;
        o1.x += r1.x; o1.y += r1.y; o1.z += r1.z; o1.w += r1.w;
    }
    if (mode == 2) {
        float sc = scal[0];
        o0.x *= sc; o0.y *= sc; o0.z *= sc; o0.w *= sc;
        o1.x *= sc; o1.y *= sc; o1.z *= sc; o1.w *= sc;
    }
    float4* op = (float4*)(out + (size_t)row * H_SIZE);
    op[t] = o0;
    op[t + 256] = o1;
}

// ---------------- RMSNorm -> fp16 hi/lo planes ----------------
__global__ __launch_bounds__(256) void rmsnorm_split_kernel(
    const float* __restrict__ in, const float* __restrict__ w,
    __half* __restrict__ oh, __half* __restrict__ ol)
{
    int row = blockIdx.x;
    int t = threadIdx.x;
    const float4* ip = (const float4*)(in + (size_t)row * H_SIZE);
    float4 v0 = ip[t];
    float4 v1 = ip[t + 256];
    float ss = v0.x*v0.x + v0.y*v0.y + v0.z*v0.z + v0.w*v0.w
             + v1.x*v1.x + v1.y*v1.y + v1.z*v1.z + v1.w*v1.w;
    #pragma unroll
    for (int o = 16; o; o >>= 1) ss += __shfl_xor_sync(0xffffffffu, ss, o);
    __shared__ float red[8];
    if ((t & 31) == 0) red[t >> 5] = ss;
    __syncthreads();
    float tot = red[0]+red[1]+red[2]+red[3]+red[4]+red[5]+red[6]+red[7];
    float inv = rsqrtf(tot * (1.0f / H_SIZE) + 1e-6f);

    const float4* w4 = (const float4*)w;
    float4 w0 = w4[t], w1 = w4[t + 256];
    size_t base = (size_t)row * H_SIZE;
    split2h(v0.x*inv*w0.x, v0.y*inv*w0.y, oh + base + t*4,     ol + base + t*4);
    split2h(v0.z*inv*w0.z, v0.w*inv*w0.w, oh + base + t*4 + 2, ol + base + t*4 + 2);
    split2h(v1.x*inv*w1.x, v1.y*inv*w1.y, oh + base + 1024 + t*4,     ol + base + 1024 + t*4);
    split2h(v1.z*inv*w1.z, v1.w*inv*w1.w, oh + base + 1024 + t*4 + 2, ol + base + 1024 + t*4 + 2);
}

// ---------------- MMA helpers ----------------
__device__ __forceinline__ void mma_fp16(float* c, const uint32_t* a, const uint32_t* b) {
    asm volatile(
        "mma.sync.aligned.m16n8k16.row.col.f32.f16.f16.f32 "
        "{%0,%1,%2,%3}, {%4,%5,%6,%7}, {%8,%9}, {%0,%1,%2,%3};\n"
        : "+f"(c[0]), "+f"(c[1]), "+f"(c[2]), "+f"(c[3])
        : "r"(a[0]), "r"(a[1]), "r"(a[2]), "r"(a[3]), "r"(b[0]), "r"(b[1]));
}

__device__ __forceinline__ void ldsm_x4(uint32_t* r, uint32_t addr) {
    asm volatile("ldmatrix.sync.aligned.m8n8.x4.shared.b16 {%0,%1,%2,%3}, [%4];"
        : "=r"(r[0]), "=r"(r[1]), "=r"(r[2]), "=r"(r[3]) : "r"(addr));
}

__device__ __forceinline__ void ldsm_x4_t(uint32_t* r, uint32_t addr) {
    asm volatile("ldmatrix.sync.aligned.m8n8.x4.trans.shared.b16 {%0,%1,%2,%3}, [%4];"
        : "=r"(r[0]), "=r"(r[1]), "=r"(r[2]), "=r"(r[3]) : "r"(addr));
}

__device__ __forceinline__ void cp16(uint32_t dst, const void* src) {
    asm volatile("cp.async.cg.shared.global [%0], [%1], 16;\n" :: "r"(dst), "l"(src));
}

// ---------------- Tensor-core GEMM: block 256x128, warp tile 64x64, 1 CTA/SM -------------
// TWOPASS: C = (Ah+Al)*Bh^T; else C = Ah*Bh^T. BK=32, cp.async 2-stage.
// bytes/MMA: 96 (2-pass), 128 (1-pass) — down from 128/192 at 32x64.

#define LDSK 40
#define A_PLANE (256*LDSK)
#define B_PLANE (128*LDSK)

template<bool TWOPASS>
__global__ __launch_bounds__(256, 1) void gemm_mma(
    const __half* __restrict__ Agh, const __half* __restrict__ Agl,
    const __half* __restrict__ Bgh,
    float* __restrict__ C, int M, int N, int K)
{
    extern __shared__ __align__(16) __half smp[];
    const int STAGE_HH = TWOPASS ? (2*A_PLANE + B_PLANE) : (A_PLANE + B_PLANE);
    const int NCHUNK   = TWOPASS ? 10 : 6;   // 16B chunks per thread per stage

    const int tid  = threadIdx.x;
    const int warp = tid >> 5, lane = tid & 31;
    const int wm = warp >> 1, wn = warp & 1;   // 4m x 2n, warp tile 64x64
    const int rowA = blockIdx.y * 256;
    const int colB = blockIdx.x * 128;

    const uint32_t smb = (uint32_t)__cvta_generic_to_shared(smp);
    const uint32_t a_off = (uint32_t)(((wm*64 + (lane & 15)) * LDSK + ((lane >> 4) * 8)) * 2);
    const uint32_t b_off = (uint32_t)(((wn*64 + ((lane >> 4) * 8) + (lane & 7)) * LDSK
                                       + (((lane >> 3) & 1) * 8)) * 2);

    float acc[4][8][4];
    #pragma unroll
    for (int i = 0; i < 4; i++)
        #pragma unroll
        for (int j = 0; j < 8; j++)
            #pragma unroll
            for (int q = 0; q < 4; q++) acc[i][j][q] = 0.f;

    // chunk map: [0,1024) Ah rows, [1024,1536) Bh rows, [1536,2560) Al rows
    #define CP_STAGE(s, k0)                                                          \
    {                                                                                \
        _Pragma("unroll")                                                            \
        for (int i = 0; i < NCHUNK; i++) {                                           \
            int cidx = tid + 256 * i;                                                \
            const __half* src; uint32_t doff;                                        \
            if (cidx < 1024) {                                                       \
                int row = cidx >> 2;                                                 \
                src = Agh + (size_t)(rowA + row) * K;                                \
                doff = (uint32_t)(row * LDSK);                                       \
            } else if (cidx < 1536) {                                                \
                int row = (cidx - 1024) >> 2;                                        \
                src = Bgh + (size_t)(colB + row) * K;                                \
                doff = (uint32_t)(A_PLANE + row * LDSK);                             \
            } else {                                                                 \
                int row = (cidx - 1536) >> 2;                                        \
                src = Agl + (size_t)(rowA + row) * K;                                \
                doff = (uint32_t)(A_PLANE + B_PLANE + row * LDSK);                   \
            }                                                                        \
            int ch = cidx & 3;                                                       \
            uint32_t dst = smb + (uint32_t)(((s) * STAGE_HH + doff + ch * 8) * 2);   \
            cp16(dst, src + (k0) + ch * 8);                                          \
        }                                                                            \
        asm volatile("cp.async.commit_group;\n" ::: "memory");                       \
    }

    const int NC = K >> 5;
    CP_STAGE(0, 0);
    for (int c = 0; c < NC; c++) {
        int s = c & 1;
        if (c + 1 < NC) {
            CP_STAGE(s ^ 1, (c + 1) * 32);
            asm volatile("cp.async.wait_group 1;\n" ::: "memory");
        } else {
            asm volatile("cp.async.wait_group 0;\n" ::: "memory");
        }
        __syncthreads();

        const uint32_t ah_b = smb + (uint32_t)((s * STAGE_HH) * 2);
        const uint32_t bh_b = ah_b + (uint32_t)(A_PLANE * 2);
        const uint32_t al_b = bh_b + (uint32_t)(B_PLANE * 2);

        #pragma unroll
        for (int kk = 0; kk < 32; kk += 16) {
            const uint32_t kko = kk * 2;
            uint32_t fa[4][4];
            uint32_t fb[4][4];
            #pragma unroll
            for (int tm = 0; tm < 4; tm++)
                ldsm_x4(fa[tm], ah_b + a_off + (uint32_t)(tm * 16 * LDSK * 2) + kko);
            #pragma unroll
            for (int p = 0; p < 4; p++)
                ldsm_x4(fb[p], bh_b + b_off + (uint32_t)(p * 16 * LDSK * 2) + kko);
            #pragma unroll
            for (int tm = 0; tm < 4; tm++)
                #pragma unroll
                for (int tn = 0; tn < 8; tn++)
                    mma_fp16(acc[tm][tn], fa[tm], &fb[tn >> 1][(tn & 1) * 2]);
            if (TWOPASS) {
                // reload A-lo into fa (register reuse)
                #pragma unroll
                for (int tm = 0; tm < 4; tm++)
                    ldsm_x4(fa[tm], al_b + a_off + (uint32_t)(tm * 16 * LDSK * 2) + kko);
                #pragma unroll
                for (int tm = 0; tm < 4; tm++)
                    #pragma unroll
                    for (int tn = 0; tn < 8; tn++)
                        mma_fp16(acc[tm][tn], fa[tm], &fb[tn >> 1][(tn & 1) * 2]);
            }
        }
        __syncthreads();
    }

    const int g = lane >> 2, t4 = lane & 3;
    #pragma unroll
    for (int tm = 0; tm < 4; tm++) {
        #pragma unroll
        for (int tn = 0; tn < 8; tn++) {
            int row = rowA + wm*64 + tm*16 + g;
            int col = colB + wn*64 + tn*8 + 2*t4;
            float2 c0 = {acc[tm][tn][0], acc[tm][tn][1]};
            float2 c1 = {acc[tm][tn][2], acc[tm][tn][3]};
            *(float2*)(C + (size_t)row * N + col)       = c0;
            *(float2*)(C + (size_t)(row + 8) * N + col) = c1;
        }
    }
}

// ---------------- RoPE ----------------
__global__ __launch_bounds__(256) void rope_kernel(float* __restrict__ buf, int nheads)
{
    int row = blockIdx.x;
    int s = row & (SEQ - 1);
    float* base = buf + (size_t)row * nheads * HD;
    for (int idx = threadIdx.x; idx < nheads * 64; idx += blockDim.x) {
        int hh = idx >> 6;
        int d = idx & 63;
        float inv = expf(-((float)d * (1.0f / 64.0f)) * 9.210340371976184f);
        float fr = (float)s * inv;
        float sn = sinf(fr), cs = cosf(fr);
        float* p = base + hh * HD + d;
        float x1 = p[0], x2 = p[64];
        p[0]  = x1 * cs - x2 * sn;
        p[64] = x2 * cs + x1 * sn;
    }
}

// ---------------- Tensor-core sliding-window GQA flash attention (unchanged R13) ---------
#define ASTR 136
#define ATTN2_SMEM ((128*ASTR*2 + 32*ASTR*4) * 2)

__global__ __launch_bounds__(256) void attn_mma_kernel(
    const float* __restrict__ Q, const float* __restrict__ K,
    const float* __restrict__ V, __half* __restrict__ Oh,
    __half* __restrict__ Ol)
{
    extern __shared__ __align__(16) __half asmem[];
    __half* Qh = asmem;
    __half* Ql = Qh + 128*ASTR;
    __half* Kh = Ql + 128*ASTR;
    __half* Kl = Kh + 32*ASTR;
    __half* Vh = Kl + 32*ASTR;
    __half* Vl = Vh + 32*ASTR;

    const int i0 = blockIdx.x * 128;
    const int h  = blockIdx.y;
    const int b  = blockIdx.z;
    const int hk = h >> 1;
    const int tid = threadIdx.x;
    const int w = tid >> 5, lane = tid & 31;
    const int g = lane >> 2, t = lane & 3;
    const float scale = 0.08838834764831845f;

    const uint32_t qh_b = (uint32_t)__cvta_generic_to_shared(Qh);
    const uint32_t ql_b = (uint32_t)__cvta_generic_to_shared(Ql);
    const uint32_t kh_b = (uint32_t)__cvta_generic_to_shared(Kh);
    const uint32_t kl_b = (uint32_t)__cvta_generic_to_shared(Kl);
    const uint32_t vh_b = (uint32_t)__cvta_generic_to_shared(Vh);
    const uint32_t vl_b = (uint32_t)__cvta_generic_to_shared(Vl);

    const uint32_t a_off  = (uint32_t)(((w*16 + (lane & 15)) * ASTR + ((lane >> 4) * 8)) * 2);
    const uint32_t kb_off = (uint32_t)((((lane >> 4) * 8 + (lane & 7)) * ASTR
                                        + ((lane >> 3) & 1) * 8) * 2);
    const uint32_t vt_off = (uint32_t)((((lane & 7) + 8 * ((lane >> 3) & 1)) * ASTR
                                        + 8 * (lane >> 4)) * 2);

    #pragma unroll
    for (int it = 0; it < 16; it++) {
        int idx = tid + 256 * it;
        int row = idx >> 5, d4 = idx & 31;
        float4 qv = *(const float4*)(Q + (size_t)(b * SEQ + i0 + row) * H_SIZE + h * HD + d4 * 4);
        int off = row * ASTR + d4 * 4;
        split2h(qv.x * scale, qv.y * scale, Qh + off,     Ql + off);
        split2h(qv.z * scale, qv.w * scale, Qh + off + 2, Ql + off + 2);
    }

    float accO[16][4];
    #pragma unroll
    for (int i = 0; i < 16; i++)
        #pragma unroll
        for (int q = 0; q < 4; q++) accO[i][q] = 0.f;
    float m0 = -1e30f, m1 = -1e30f, l0 = 0.f, l1 = 0.f;

    int jstart = i0 - (WIN - 1);
    if (jstart < 0) jstart = 0;
    jstart &= ~31;
    const int r0 = i0 + w*16 + g;
    const int r1 = r0 + 8;

    for (int j0 = jstart; j0 < i0 + 128; j0 += 32) {
        __syncthreads();
        #pragma unroll
        for (int it = 0; it < 4; it++) {
            int idx = tid + 256 * it;
            int row = idx >> 5, d4 = idx & 31;
            size_t goff = (size_t)(b * SEQ + j0 + row) * (NKV * HD) + hk * HD + d4 * 4;
            float4 kv = *(const float4*)(K + goff);
            float4 vv = *(const float4*)(V + goff);
            int off = row * ASTR + d4 * 4;
            split2h(kv.x, kv.y, Kh + off,     Kl + off);
            split2h(kv.z, kv.w, Kh + off + 2, Kl + off + 2);
            split2h(vv.x, vv.y, Vh + off,     Vl + off);
            split2h(vv.z, vv.w, Vh + off + 2, Vl + off + 2);
        }
        __syncthreads();

        float accS[4][4];
        #pragma unroll
        for (int nt = 0; nt < 4; nt++)
            #pragma unroll
            for (int q = 0; q < 4; q++) accS[nt][q] = 0.f;

        #pragma unroll
        for (int ks = 0; ks < 8; ks++) {
            const uint32_t kko = (uint32_t)(ks * 32);
            uint32_t fa[4], fal[4], fb[2][4], fbl[2][4];
            ldsm_x4(fa,  qh_b + a_off + kko);
            ldsm_x4(fal, ql_b + a_off + kko);
            ldsm_x4(fb[0],  kh_b + kb_off + kko);
            ldsm_x4(fb[1],  kh_b + kb_off + (uint32_t)(16 * ASTR * 2) + kko);
            ldsm_x4(fbl[0], kl_b + kb_off + kko);
            ldsm_x4(fbl[1], kl_b + kb_off + (uint32_t)(16 * ASTR * 2) + kko);
            #pragma unroll
            for (int nt = 0; nt < 4; nt++) {
                mma_fp16(accS[nt], fa,  &fb[nt >> 1][(nt & 1) * 2]);
                mma_fp16(accS[nt], fal, &fb[nt >> 1][(nt & 1) * 2]);
                mma_fp16(accS[nt], fa,  &fbl[nt >> 1][(nt & 1) * 2]);
            }
        }

        #pragma unroll
        for (int nt = 0; nt < 4; nt++) {
            int jc0 = j0 + nt * 8 + 2 * t;
            int jc1 = jc0 + 1;
            accS[nt][0] = (jc0 <= r0 && r0 - jc0 < WIN) ? accS[nt][0] : -1e30f;
            accS[nt][1] = (jc1 <= r0 && r0 - jc1 < WIN) ? accS[nt][1] : -1e30f;
            accS[nt][2] = (jc0 <= r1 && r1 - jc0 < WIN) ? accS[nt][2] : -1e30f;
            accS[nt][3] = (jc1 <= r1 && r1 - jc1 < WIN) ? accS[nt][3] : -1e30f;
        }

        float mt0 = m0, mt1 = m1;
        #pragma unroll
        for (int nt = 0; nt < 4; nt++) {
            mt0 = fmaxf(mt0, fmaxf(accS[nt][0], accS[nt][1]));
            mt1 = fmaxf(mt1, fmaxf(accS[nt][2], accS[nt][3]));
        }
        mt0 = fmaxf(mt0, __shfl_xor_sync(0xffffffffu, mt0, 1));
        mt0 = fmaxf(mt0, __shfl_xor_sync(0xffffffffu, mt0, 2));
        mt1 = fmaxf(mt1, __shfl_xor_sync(0xffffffffu, mt1, 1));
        mt1 = fmaxf(mt1, __shfl_xor_sync(0xffffffffu, mt1, 2));
        float alpha0 = __expf(m0 - mt0);
        float alpha1 = __expf(m1 - mt1);
        m0 = mt0; m1 = mt1;

        float p[4][4];
        float ps0 = 0.f, ps1 = 0.f;
        #pragma unroll
        for (int nt = 0; nt < 4; nt++) {
            p[nt][0] = __expf(accS[nt][0] - mt0);
            p[nt][1] = __expf(accS[nt][1] - mt0);
            p[nt][2] = __expf(accS[nt][2] - mt1);
            p[nt][3] = __expf(accS[nt][3] - mt1);
            ps0 += p[nt][0] + p[nt][1];
            ps1 += p[nt][2] + p[nt][3];
        }
        ps0 += __shfl_xor_sync(0xffffffffu, ps0, 1);
        ps0 += __shfl_xor_sync(0xffffffffu, ps0, 2);
        ps1 += __shfl_xor_sync(0xffffffffu, ps1, 1);
        ps1 += __shfl_xor_sync(0xffffffffu, ps1, 2);
        l0 = l0 * alpha0 + ps0;
        l1 = l1 * alpha1 + ps1;

        #pragma unroll
        for (int i = 0; i < 16; i++) {
            accO[i][0] *= alpha0; accO[i][1] *= alpha0;
            accO[i][2] *= alpha1; accO[i][3] *= alpha1;
        }

        uint32_t ph[2][4], pl[2][4];
        #pragma unroll
        for (int kb = 0; kb < 2; kb++) {
            #pragma unroll
            for (int q = 0; q < 4; q++) {
                int nt = 2*kb + (q >> 1);
                int e0 = (q & 1) * 2;
                float v0 = p[nt][e0], v1 = p[nt][e0 + 1];
                __half h0 = __float2half(v0), h1 = __float2half(v1);
                __half lo0 = __float2half(v0 - __half2float(h0));
                __half lo1 = __float2half(v1 - __half2float(h1));
                int ridx = (q >> 1) * 2 + (q & 1);
                __half2 hh = __halves2half2(h0, h1);
                __half2 ll = __halves2half2(lo0, lo1);
                ph[kb][ridx] = *(uint32_t*)&hh;
                pl[kb][ridx] = *(uint32_t*)&ll;
            }
        }

        #pragma unroll
        for (int kb = 0; kb < 2; kb++) {
            #pragma unroll
            for (int dg = 0; dg < 8; dg++) {
                uint32_t vb[4], vbl[4];
                uint32_t voff = vt_off + (uint32_t)((kb * 16 * ASTR + dg * 16) * 2);
                ldsm_x4_t(vb,  vh_b + voff);
                ldsm_x4_t(vbl, vl_b + voff);
                mma_fp16(accO[2*dg],     ph[kb], &vb[0]);
                mma_fp16(accO[2*dg],     pl[kb], &vb[0]);
                mma_fp16(accO[2*dg],     ph[kb], &vbl[0]);
                mma_fp16(accO[2*dg + 1], ph[kb], &vb[2]);
                mma_fp16(accO[2*dg + 1], pl[kb], &vb[2]);
                mma_fp16(accO[2*dg + 1], ph[kb], &vbl[2]);
            }
        }
    }

    float li0 = 1.0f / l0, li1 = 1.0f / l1;
    size_t ob0 = (size_t)(b * SEQ + i0 + w*16 + g) * H_SIZE + h * HD;
    size_t ob1 = ob0 + (size_t)8 * H_SIZE;
    #pragma unroll
    for (int nt = 0; nt < 16; nt++) {
        int dim = nt * 8 + 2 * t;
        split2h(accO[nt][0] * li0, accO[nt][1] * li0, Oh + ob0 + dim, Ol + ob0 + dim);
        split2h(accO[nt][2] * li1, accO[nt][3] * li1, Oh + ob1 + dim, Ol + ob1 + dim);
    }
}

// ---------------- GeGLU: fp16 hi plane out ----------------
__device__ __forceinline__ float gelu_exact(float x) {
    return 0.5f * x * (1.0f + erff(x * 0.7071067811865476f));
}
__global__ __launch_bounds__(256) void geglu_kernel(
    const float* __restrict__ g, const float* __restrict__ u,
    __half* __restrict__ oh, int n4)
{
    int i = blockIdx.x * blockDim.x + threadIdx.x;
    int stride = gridDim.x * blockDim.x;
    for (; i < n4; i += stride) {
        float4 gv = ((const float4*)g)[i];
        float4 uv = ((const float4*)u)[i];
        float r0 = gelu_exact(gv.x) * uv.x;
        float r1 = gelu_exact(gv.y) * uv.y;
        float r2 = gelu_exact(gv.z) * uv.z;
        float r3 = gelu_exact(gv.w) * uv.w;
        *(__half2*)(oh + i*4)     = __halves2half2(__float2half(r0), __float2half(r1));
        *(__half2*)(oh + i*4 + 2) = __halves2half2(__float2half(r2), __float2half(r3));
    }
}

// ---------------- launch ----------------
extern "C" void kernel_launch(void* const* d_in, const int* in_sizes, int n_in,
                              void* d_out, int out_size)
{
    const float* x    = (const float*)d_in[0];
    const float* wq   = (const float*)d_in[1];
    const float* wk   = (const float*)d_in[2];
    const float* wv   = (const float*)d_in[3];
    const float* wo   = (const float*)d_in[4];
    const float* w_in = (const float*)d_in[5];
    const float* w_pa = (const float*)d_in[6];
    const float* w_pf = (const float*)d_in[7];
    const float* w_pff= (const float*)d_in[8];
    const float* wg   = (const float*)d_in[9];
    const float* wu   = (const float*)d_in[10];
    const float* wd   = (const float*)d_in[11];
    const float* lsc  = (const float*)d_in[12];
    float* out = (float*)d_out;

    float *q, *k, *v, *attnout, *h2, *gate, *up, *ffnout;
    cudaGetSymbolAddress((void**)&q,       g_q);
    cudaGetSymbolAddress((void**)&k,       g_k);
    cudaGetSymbolAddress((void**)&v,       g_v);
    cudaGetSymbolAddress((void**)&attnout, g_attnout);
    cudaGetSymbolAddress((void**)&h2,      g_h2);
    cudaGetSymbolAddress((void**)&gate,    g_gate);
    cudaGetSymbolAddress((void**)&up,      g_up);
    cudaGetSymbolAddress((void**)&ffnout,  g_ffnout);

    __half *h_h, *h_l, *attn_h, *attn_l, *ffnin_h, *ffnin_l, *gact_h;
    __half *pwq, *pwk, *pwv, *pwo, *pwg, *pwu, *pwd;
    cudaGetSymbolAddress((void**)&h_h, g_h_h);         cudaGetSymbolAddress((void**)&h_l, g_h_l);
    cudaGetSymbolAddress((void**)&attn_h, g_attn_h);   cudaGetSymbolAddress((void**)&attn_l, g_attn_l);
    cudaGetSymbolAddress((void**)&ffnin_h, g_ffnin_h); cudaGetSymbolAddress((void**)&ffnin_l, g_ffnin_l);
    cudaGetSymbolAddress((void**)&gact_h, g_gact_h);
    cudaGetSymbolAddress((void**)&pwq, g_wq);
    cudaGetSymbolAddress((void**)&pwk, g_wk);
    cudaGetSymbolAddress((void**)&pwv, g_wv);
    cudaGetSymbolAddress((void**)&pwo, g_wo);
    cudaGetSymbolAddress((void**)&pwg, g_wg);
    cudaGetSymbolAddress((void**)&pwu, g_wu);
    cudaGetSymbolAddress((void**)&pwd, g_wd);

    const int smem2 = 2 * (2*A_PLANE + B_PLANE) * 2;
    const int smem1 = 2 * (A_PLANE + B_PLANE) * 2;
    cudaFuncSetAttribute(attn_mma_kernel, cudaFuncAttributeMaxDynamicSharedMemorySize, ATTN2_SMEM);
    cudaFuncSetAttribute(gemm_mma<true>,  cudaFuncAttributeMaxDynamicSharedMemorySize, smem2);
    cudaFuncSetAttribute(gemm_mma<false>, cudaFuncAttributeMaxDynamicSharedMemorySize, smem1);

    // weight planes (fp16)
    wsplit_kernel<<<2048, 256>>>(wq, pwq, H_SIZE*H_SIZE/4);
    wsplit_kernel<<<1024, 256>>>(wk, pwk, NKV*HD*H_SIZE/4);
    wsplit_kernel<<<1024, 256>>>(wv, pwv, NKV*HD*H_SIZE/4);
    wsplit_kernel<<<2048, 256>>>(wo, pwo, H_SIZE*H_SIZE/4);
    wsplit_kernel<<<4096, 256>>>(wg, pwg, INTER_SZ*H_SIZE/4);
    wsplit_kernel<<<4096, 256>>>(wu, pwu, INTER_SZ*H_SIZE/4);
    wsplit_kernel<<<4096, 256>>>(wd, pwd, H_SIZE*INTER_SZ/4);

    // h = rmsnorm(x, w_in) -> fp16 hi/lo planes
    rmsnorm_split_kernel<<<NROWS, 256>>>(x, w_in, h_h, h_l);
    // QKV (2-pass)
    gemm_mma<true><<<dim3(H_SIZE/128, NROWS/256), 256, smem2>>>(h_h, h_l, pwq, q, NROWS, H_SIZE, H_SIZE);
    gemm_mma<true><<<dim3((NKV*HD)/128, NROWS/256), 256, smem2>>>(h_h, h_l, pwk, k, NROWS, NKV*HD, H_SIZE);
    gemm_mma<true><<<dim3((NKV*HD)/128, NROWS/256), 256, smem2>>>(h_h, h_l, pwv, v, NROWS, NKV*HD, H_SIZE);
    // RoPE
    rope_kernel<<<NROWS, 256>>>(q, NQ);
    rope_kernel<<<NROWS, 256>>>(k, NKV);
    // tensor-core attention -> fp16 planes
    attn_mma_kernel<<<dim3(SEQ/128, NQ, BATCH), 256, ATTN2_SMEM>>>(q, k, v, attn_h, attn_l);
    // WO (2-pass)
    gemm_mma<true><<<dim3(H_SIZE/128, NROWS/256), 256, smem2>>>(attn_h, attn_l, pwo, attnout, NROWS, H_SIZE, H_SIZE);
    // h2 = x + rmsnorm(attnout, w_pa)
    rmsnorm_kernel<<<NROWS, 256>>>(attnout, w_pa, x, nullptr, h2, 1);
    // ffn_in = rmsnorm(h2, w_pf) -> fp16 planes
    rmsnorm_split_kernel<<<NROWS, 256>>>(h2, w_pf, ffnin_h, ffnin_l);
    // gate/up GEMMs (1-pass fp16)
    gemm_mma<false><<<dim3(INTER_SZ/128, NROWS/256), 256, smem1>>>(ffnin_h, nullptr, pwg, gate, NROWS, INTER_SZ, H_SIZE);
    gemm_mma<false><<<dim3(INTER_SZ/128, NROWS/256), 256, smem1>>>(ffnin_h, nullptr, pwu, up, NROWS, INTER_SZ, H_SIZE);
    // act = gelu(gate) * up -> fp16 hi plane
    geglu_kernel<<<8192, 256>>>(gate, up, gact_h, (NROWS * INTER_SZ) / 4);
    // down projection (1-pass fp16, K = INTER)
    gemm_mma<false><<<dim3(H_SIZE/128, NROWS/256), 256, smem1>>>(gact_h, nullptr, pwd, ffnout, NROWS, H_SIZE, INTER_SZ);
    // out = (h2 + rmsnorm(ffnout, w_pff)) * layer_scalar
    rmsnorm_kernel<<<NROWS, 256>>>(ffnout, w_pff, h2, lsc, out, 2);
}

// round 15
// speedup vs baseline: 1.0012x; 1.0012x over previous
#include <cuda_runtime.h>
#include <cuda_fp16.h>
#include <stdint.h>
#include <math.h>

#define H_SIZE 2048
#define INTER_SZ 8192
#define NQ 16
#define NKV 8
#define HD 128
#define SEQ 2048
#define BATCH 2
#define NROWS (BATCH*SEQ)
#define WIN 1024

// ---------------- fp32 scratch ----------------
__device__ float g_q[NROWS*H_SIZE];
__device__ float g_k[NROWS*NKV*HD];
__device__ float g_v[NROWS*NKV*HD];
__device__ float g_attnout[NROWS*H_SIZE];
__device__ float g_h2[NROWS*H_SIZE];
__device__ float g_gate[NROWS*INTER_SZ];
__device__ float g_up[NROWS*INTER_SZ];
__device__ float g_ffnout[NROWS*H_SIZE];

// ---------------- fp16 planes ----------------
__device__ __half g_h_h[NROWS*H_SIZE],      g_h_l[NROWS*H_SIZE];
__device__ __half g_attn_h[NROWS*H_SIZE],   g_attn_l[NROWS*H_SIZE];
__device__ __half g_ffnin_h[NROWS*H_SIZE],  g_ffnin_l[NROWS*H_SIZE];
__device__ __half g_gact_h[NROWS*INTER_SZ];
__device__ __half g_wq[H_SIZE*H_SIZE];
__device__ __half g_wk[NKV*HD*H_SIZE];
__device__ __half g_wv[NKV*HD*H_SIZE];
__device__ __half g_wo[H_SIZE*H_SIZE];
__device__ __half g_wg[INTER_SZ*H_SIZE];
__device__ __half g_wu[INTER_SZ*H_SIZE];
__device__ __half g_wd[H_SIZE*INTER_SZ];

// ---------------- helpers ----------------
__device__ __forceinline__ void split2h(float a, float b, __half* hi, __half* lo) {
    __half ha = __float2half(a), hb = __float2half(b);
    __half la = __float2half(a - __half2float(ha));
    __half lb = __float2half(b - __half2float(hb));
    *(__half2*)hi = __halves2half2(ha, hb);
    *(__half2*)lo = __halves2half2(la, lb);
}

__global__ __launch_bounds__(256) void wsplit_kernel(
    const float* __restrict__ in, __half* __restrict__ out, int n4)
{
    int i = blockIdx.x * blockDim.x + threadIdx.x;
    int stride = gridDim.x * blockDim.x;
    for (; i < n4; i += stride) {
        float4 v = ((const float4*)in)[i];
        *(__half2*)(out + i*4)     = __halves2half2(__float2half(v.x), __float2half(v.y));
        *(__half2*)(out + i*4 + 2) = __halves2half2(__float2half(v.z), __float2half(v.w));
    }
}

// ---------------- RMSNorm fp32 out ----------------
__global__ __launch_bounds__(256) void rmsnorm_kernel(
    const float* __restrict__ in, const float* __restrict__ w,
    const float* __restrict__ res, const float* __restrict__ scal,
    float* __restrict__ out, int mode)
{
    int row = blockIdx.x;
    int t = threadIdx.x;
    const float4* ip = (const float4*)(in + (size_t)row * H_SIZE);
    float4 v0 = ip[t];
    float4 v1 = ip[t + 256];
    float ss = v0.x*v0.x + v0.y*v0.y + v0.z*v0.z + v0.w*v0.w
             + v1.x*v1.x + v1.y*v1.y + v1.z*v1.z + v1.w*v1.w;
    #pragma unroll
    for (int o = 16; o; o >>= 1) ss += __shfl_xor_sync(0xffffffffu, ss, o);
    __shared__ float red[8];
    if ((t & 31) == 0) red[t >> 5] = ss;
    __syncthreads();
    float tot = red[0]+red[1]+red[2]+red[3]+red[4]+red[5]+red[6]+red[7];
    float inv = rsqrtf(tot * (1.0f / H_SIZE) + 1e-6f);

    const float4* w4 = (const float4*)w;
    float4 w0 = w4[t], w1 = w4[t + 256];
    float4 o0, o1;
    o0.x = v0.x*inv*w0.x; o0.y = v0.y*inv*w0.y; o0.z = v0.z*inv*w0.z; o0.w = v0.w*inv*w0.w;
    o1.x = v1.x*inv*w1.x; o1.y = v1.y*inv*w1.y; o1.z = v1.z*inv*w1.z; o1.w = v1.w*inv*w1.w;
    if (mode >= 1) {
        const float4* rp = (const float4*)(res + (size_t)row * H_SIZE);
        float4 r0 = rp[t], r1 = rp[t + 256];
        o0.x += r0.x; o0.y += r0.y; o0.z += r0.z; o0.w += r0.w;
        o1.x += r1.x; o1.y += r1.y; o1.z += r1.z; o1.w += r1.w;
    }
    if (mode == 2) {
        float sc = scal[0];
        o0.x *= sc; o0.y *= sc; o0.z *= sc; o0.w *= sc;
        o1.x *= sc; o1.y *= sc; o1.z *= sc; o1.w *= sc;
    }
    float4* op = (float4*)(out + (size_t)row * H_SIZE);
    op[t] = o0;
    op[t + 256] = o1;
}

// ---------------- RMSNorm -> fp16 hi/lo planes ----------------
__global__ __launch_bounds__(256) void rmsnorm_split_kernel(
    const float* __restrict__ in, const float* __restrict__ w,
    __half* __restrict__ oh, __half* __restrict__ ol)
{
    int row = blockIdx.x;
    int t = threadIdx.x;
    const float4* ip = (const float4*)(in + (size_t)row * H_SIZE);
    float4 v0 = ip[t];
    float4 v1 = ip[t + 256];
    float ss = v0.x*v0.x + v0.y*v0.y + v0.z*v0.z + v0.w*v0.w
             + v1.x*v1.x + v1.y*v1.y + v1.z*v1.z + v1.w*v1.w;
    #pragma unroll
    for (int o = 16; o; o >>= 1) ss += __shfl_xor_sync(0xffffffffu, ss, o);
    __shared__ float red[8];
    if ((t & 31) == 0) red[t >> 5] = ss;
    __syncthreads();
    float tot = red[0]+red[1]+red[2]+red[3]+red[4]+red[5]+red[6]+red[7];
    float inv = rsqrtf(tot * (1.0f / H_SIZE) + 1e-6f);

    const float4* w4 = (const float4*)w;
    float4 w0 = w4[t], w1 = w4[t + 256];
    size_t base = (size_t)row * H_SIZE;
    split2h(v0.x*inv*w0.x, v0.y*inv*w0.y, oh + base + t*4,     ol + base + t*4);
    split2h(v0.z*inv*w0.z, v0.w*inv*w0.w, oh + base + t*4 + 2, ol + base + t*4 + 2);
    split2h(v1.x*inv*w1.x, v1.y*inv*w1.y, oh + base + 1024 + t*4,     ol + base + 1024 + t*4);
    split2h(v1.z*inv*w1.z, v1.w*inv*w1.w, oh + base + 1024 + t*4 + 2, ol + base + 1024 + t*4 + 2);
}

// ---------------- MMA helpers ----------------
__device__ __forceinline__ void mma_fp16(float* c, const uint32_t* a, const uint32_t* b) {
    asm volatile(
        "mma.sync.aligned.m16n8k16.row.col.f32.f16.f16.f32 "
        "{%0,%1,%2,%3}, {%4,%5,%6,%7}, {%8,%9}, {%0,%1,%2,%3};\n"
        : "+f"(c[0]), "+f"(c[1]), "+f"(c[2]), "+f"(c[3])
        : "r"(a[0]), "r"(a[1]), "r"(a[2]), "r"(a[3]), "r"(b[0]), "r"(b[1]));
}

__device__ __forceinline__ void ldsm_x4(uint32_t* r, uint32_t addr) {
    asm volatile("ldmatrix.sync.aligned.m8n8.x4.shared.b16 {%0,%1,%2,%3}, [%4];"
        : "=r"(r[0]), "=r"(r[1]), "=r"(r[2]), "=r"(r[3]) : "r"(addr));
}

__device__ __forceinline__ void ldsm_x4_t(uint32_t* r, uint32_t addr) {
    asm volatile("ldmatrix.sync.aligned.m8n8.x4.trans.shared.b16 {%0,%1,%2,%3}, [%4];"
        : "=r"(r[0]), "=r"(r[1]), "=r"(r[2]), "=r"(r[3]) : "r"(addr));
}

__device__ __forceinline__ void cp16(uint32_t dst, const void* src) {
    asm volatile("cp.async.cg.shared.global [%0], [%1], 16;\n" :: "r"(dst), "l"(src));
}

// ---------------- Tensor-core GEMM: block 256x128, warp tile 64x64, 1 CTA/SM -------------
// TWOPASS: C = (Ah+Al)*Bh^T; else C = Ah*Bh^T. BK=32, cp.async 2-stage.
// bytes/MMA: 96 (2-pass), 128 (1-pass) — down from 128/192 at 32x64.

#define LDSK 40
#define A_PLANE (256*LDSK)
#define B_PLANE (128*LDSK)

template<bool TWOPASS>
__global__ __launch_bounds__(256, 1) void gemm_mma(
    const __half* __restrict__ Agh, const __half* __restrict__ Agl,
    const __half* __restrict__ Bgh,
    float* __restrict__ C, int M, int N, int K)
{
    extern __shared__ __align__(16) __half smp[];
    const int STAGE_HH = TWOPASS ? (2*A_PLANE + B_PLANE) : (A_PLANE + B_PLANE);
    const int NCHUNK   = TWOPASS ? 10 : 6;   // 16B chunks per thread per stage

    const int tid  = threadIdx.x;
    const int warp = tid >> 5, lane = tid & 31;
    const int wm = warp >> 1, wn = warp & 1;   // 4m x 2n, warp tile 64x64
    const int rowA = blockIdx.y * 256;
    const int colB = blockIdx.x * 128;

    const uint32_t smb = (uint32_t)__cvta_generic_to_shared(smp);
    const uint32_t a_off = (uint32_t)(((wm*64 + (lane & 15)) * LDSK + ((lane >> 4) * 8)) * 2);
    const uint32_t b_off = (uint32_t)(((wn*64 + ((lane >> 4) * 8) + (lane & 7)) * LDSK
                                       + (((lane >> 3) & 1) * 8)) * 2);

    float acc[4][8][4];
    #pragma unroll
    for (int i = 0; i < 4; i++)
        #pragma unroll
        for (int j = 0; j < 8; j++)
            #pragma unroll
            for (int q = 0; q < 4; q++) acc[i][j][q] = 0.f;

    // chunk map: [0,1024) Ah rows, [1024,1536) Bh rows, [1536,2560) Al rows
    #define CP_STAGE(s, k0)                                                          \
    {                                                                                \
        _Pragma("unroll")                                                            \
        for (int i = 0; i < NCHUNK; i++) {                                           \
            int cidx = tid + 256 * i;                                                \
            const __half* src; uint32_t doff;                                        \
            if (cidx < 1024) {                                                       \
                int row = cidx >> 2;                                                 \
                src = Agh + (size_t)(rowA + row) * K;                                \
                doff = (uint32_t)(row * LDSK);                                       \
            } else if (cidx < 1536) {                                                \
                int row = (cidx - 1024) >> 2;                                        \
                src = Bgh + (size_t)(colB + row) * K;                                \
                doff = (uint32_t)(A_PLANE + row * LDSK);                             \
            } else {                                                                 \
                int row = (cidx - 1536) >> 2;                                        \
                src = Agl + (size_t)(rowA + row) * K;                                \
                doff = (uint32_t)(A_PLANE + B_PLANE + row * LDSK);                   \
            }                                                                        \
            int ch = cidx & 3;                                                       \
            uint32_t dst = smb + (uint32_t)(((s) * STAGE_HH + doff + ch * 8) * 2);   \
            cp16(dst, src + (k0) + ch * 8);                                          \
        }                                                                            \
        asm volatile("cp.async.commit_group;\n" ::: "memory");                       \
    }

    const int NC = K >> 5;
    CP_STAGE(0, 0);
    for (int c = 0; c < NC; c++) {
        int s = c & 1;
        if (c + 1 < NC) {
            CP_STAGE(s ^ 1, (c + 1) * 32);
            asm volatile("cp.async.wait_group 1;\n" ::: "memory");
        } else {
            asm volatile("cp.async.wait_group 0;\n" ::: "memory");
        }
        __syncthreads();

        const uint32_t ah_b = smb + (uint32_t)((s * STAGE_HH) * 2);
        const uint32_t bh_b = ah_b + (uint32_t)(A_PLANE * 2);
        const uint32_t al_b = bh_b + (uint32_t)(B_PLANE * 2);

        #pragma unroll
        for (int kk = 0; kk < 32; kk += 16) {
            const uint32_t kko = kk * 2;
            uint32_t fa[4][4];
            uint32_t fb[4][4];
            #pragma unroll
            for (int tm = 0; tm < 4; tm++)
                ldsm_x4(fa[tm], ah_b + a_off + (uint32_t)(tm * 16 * LDSK * 2) + kko);
            #pragma unroll
            for (int p = 0; p < 4; p++)
                ldsm_x4(fb[p], bh_b + b_off + (uint32_t)(p * 16 * LDSK * 2) + kko);
            #pragma unroll
            for (int tm = 0; tm < 4; tm++)
                #pragma unroll
                for (int tn = 0; tn < 8; tn++)
                    mma_fp16(acc[tm][tn], fa[tm], &fb[tn >> 1][(tn & 1) * 2]);
            if (TWOPASS) {
                // reload A-lo into fa (register reuse)
                #pragma unroll
                for (int tm = 0; tm < 4; tm++)
                    ldsm_x4(fa[tm], al_b + a_off + (uint32_t)(tm * 16 * LDSK * 2) + kko);
                #pragma unroll
                for (int tm = 0; tm < 4; tm++)
                    #pragma unroll
                    for (int tn = 0; tn < 8; tn++)
                        mma_fp16(acc[tm][tn], fa[tm], &fb[tn >> 1][(tn & 1) * 2]);
            }
        }
        __syncthreads();
    }

    const int g = lane >> 2, t4 = lane & 3;
    #pragma unroll
    for (int tm = 0; tm < 4; tm++) {
        #pragma unroll
        for (int tn = 0; tn < 8; tn++) {
            int row = rowA + wm*64 + tm*16 + g;
            int col = colB + wn*64 + tn*8 + 2*t4;
            float2 c0 = {acc[tm][tn][0], acc[tm][tn][1]};
            float2 c1 = {acc[tm][tn][2], acc[tm][tn][3]};
            *(float2*)(C + (size_t)row * N + col)       = c0;
            *(float2*)(C + (size_t)(row + 8) * N + col) = c1;
        }
    }
}

// ---------------- RoPE ----------------
__global__ __launch_bounds__(256) void rope_kernel(float* __restrict__ buf, int nheads)
{
    int row = blockIdx.x;
    int s = row & (SEQ - 1);
    float* base = buf + (size_t)row * nheads * HD;
    for (int idx = threadIdx.x; idx < nheads * 64; idx += blockDim.x) {
        int hh = idx >> 6;
        int d = idx & 63;
        float inv = expf(-((float)d * (1.0f / 64.0f)) * 9.210340371976184f);
        float fr = (float)s * inv;
        float sn = sinf(fr), cs = cosf(fr);
        float* p = base + hh * HD + d;
        float x1 = p[0], x2 = p[64];
        p[0]  = x1 * cs - x2 * sn;
        p[64] = x2 * cs + x1 * sn;
    }
}

// ---------------- Tensor-core sliding-window GQA flash attention (unchanged R13) ---------
#define ASTR 136
#define ATTN2_SMEM ((128*ASTR*2 + 32*ASTR*4) * 2)

__global__ __launch_bounds__(256) void attn_mma_kernel(
    const float* __restrict__ Q, const float* __restrict__ K,
    const float* __restrict__ V, __half* __restrict__ Oh,
    __half* __restrict__ Ol)
{
    extern __shared__ __align__(16) __half asmem[];
    __half* Qh = asmem;
    __half* Ql = Qh + 128*ASTR;
    __half* Kh = Ql + 128*ASTR;
    __half* Kl = Kh + 32*ASTR;
    __half* Vh = Kl + 32*ASTR;
    __half* Vl = Vh + 32*ASTR;

    const int i0 = blockIdx.x * 128;
    const int h  = blockIdx.y;
    const int b  = blockIdx.z;
    const int hk = h >> 1;
    const int tid = threadIdx.x;
    const int w = tid >> 5, lane = tid & 31;
    const int g = lane >> 2, t = lane & 3;
    const float scale = 0.08838834764831845f;

    const uint32_t qh_b = (uint32_t)__cvta_generic_to_shared(Qh);
    const uint32_t ql_b = (uint32_t)__cvta_generic_to_shared(Ql);
    const uint32_t kh_b = (uint32_t)__cvta_generic_to_shared(Kh);
    const uint32_t kl_b = (uint32_t)__cvta_generic_to_shared(Kl);
    const uint32_t vh_b = (uint32_t)__cvta_generic_to_shared(Vh);
    const uint32_t vl_b = (uint32_t)__cvta_generic_to_shared(Vl);

    const uint32_t a_off  = (uint32_t)(((w*16 + (lane & 15)) * ASTR + ((lane >> 4) * 8)) * 2);
    const uint32_t kb_off = (uint32_t)((((lane >> 4) * 8 + (lane & 7)) * ASTR
                                        + ((lane >> 3) & 1) * 8) * 2);
    const uint32_t vt_off = (uint32_t)((((lane & 7) + 8 * ((lane >> 3) & 1)) * ASTR
                                        + 8 * (lane >> 4)) * 2);

    #pragma unroll
    for (int it = 0; it < 16; it++) {
        int idx = tid + 256 * it;
        int row = idx >> 5, d4 = idx & 31;
        float4 qv = *(const float4*)(Q + (size_t)(b * SEQ + i0 + row) * H_SIZE + h * HD + d4 * 4);
        int off = row * ASTR + d4 * 4;
        split2h(qv.x * scale, qv.y * scale, Qh + off,     Ql + off);
        split2h(qv.z * scale, qv.w * scale, Qh + off + 2, Ql + off + 2);
    }

    float accO[16][4];
    #pragma unroll
    for (int i = 0; i < 16; i++)
        #pragma unroll
        for (int q = 0; q < 4; q++) accO[i][q] = 0.f;
    float m0 = -1e30f, m1 = -1e30f, l0 = 0.f, l1 = 0.f;

    int jstart = i0 - (WIN - 1);
    if (jstart < 0) jstart = 0;
    jstart &= ~31;
    const int r0 = i0 + w*16 + g;
    const int r1 = r0 + 8;

    for (int j0 = jstart; j0 < i0 + 128; j0 += 32) {
        __syncthreads();
        #pragma unroll
        for (int it = 0; it < 4; it++) {
            int idx = tid + 256 * it;
            int row = idx >> 5, d4 = idx & 31;
            size_t goff = (size_t)(b * SEQ + j0 + row) * (NKV * HD) + hk * HD + d4 * 4;
            float4 kv = *(const float4*)(K + goff);
            float4 vv = *(const float4*)(V + goff);
            int off = row * ASTR + d4 * 4;
            split2h(kv.x, kv.y, Kh + off,     Kl + off);
            split2h(kv.z, kv.w, Kh + off + 2, Kl + off + 2);
            split2h(vv.x, vv.y, Vh + off,     Vl + off);
            split2h(vv.z, vv.w, Vh + off + 2, Vl + off + 2);
        }
        __syncthreads();

        float accS[4][4];
        #pragma unroll
        for (int nt = 0; nt < 4; nt++)
            #pragma unroll
            for (int q = 0; q < 4; q++) accS[nt][q] = 0.f;

        #pragma unroll
        for (int ks = 0; ks < 8; ks++) {
            const uint32_t kko = (uint32_t)(ks * 32);
            uint32_t fa[4], fal[4], fb[2][4], fbl[2][4];
            ldsm_x4(fa,  qh_b + a_off + kko);
            ldsm_x4(fal, ql_b + a_off + kko);
            ldsm_x4(fb[0],  kh_b + kb_off + kko);
            ldsm_x4(fb[1],  kh_b + kb_off + (uint32_t)(16 * ASTR * 2) + kko);
            ldsm_x4(fbl[0], kl_b + kb_off + kko);
            ldsm_x4(fbl[1], kl_b + kb_off + (uint32_t)(16 * ASTR * 2) + kko);
            #pragma unroll
            for (int nt = 0; nt < 4; nt++) {
                mma_fp16(accS[nt], fa,  &fb[nt >> 1][(nt & 1) * 2]);
                mma_fp16(accS[nt], fal, &fb[nt >> 1][(nt & 1) * 2]);
                mma_fp16(accS[nt], fa,  &fbl[nt >> 1][(nt & 1) * 2]);
            }
        }

        #pragma unroll
        for (int nt = 0; nt < 4; nt++) {
            int jc0 = j0 + nt * 8 + 2 * t;
            int jc1 = jc0 + 1;
            accS[nt][0] = (jc0 <= r0 && r0 - jc0 < WIN) ? accS[nt][0] : -1e30f;
            accS[nt][1] = (jc1 <= r0 && r0 - jc1 < WIN) ? accS[nt][1] : -1e30f;
            accS[nt][2] = (jc0 <= r1 && r1 - jc0 < WIN) ? accS[nt][2] : -1e30f;
            accS[nt][3] = (jc1 <= r1 && r1 - jc1 < WIN) ? accS[nt][3] : -1e30f;
        }

        float mt0 = m0, mt1 = m1;
        #pragma unroll
        for (int nt = 0; nt < 4; nt++) {
            mt0 = fmaxf(mt0, fmaxf(accS[nt][0], accS[nt][1]));
            mt1 = fmaxf(mt1, fmaxf(accS[nt][2], accS[nt][3]));
        }
        mt0 = fmaxf(mt0, __shfl_xor_sync(0xffffffffu, mt0, 1));
        mt0 = fmaxf(mt0, __shfl_xor_sync(0xffffffffu, mt0, 2));
        mt1 = fmaxf(mt1, __shfl_xor_sync(0xffffffffu, mt1, 1));
        mt1 = fmaxf(mt1, __shfl_xor_sync(0xffffffffu, mt1, 2));
        float alpha0 = __expf(m0 - mt0);
        float alpha1 = __expf(m1 - mt1);
        m0 = mt0; m1 = mt1;

        float p[4][4];
        float ps0 = 0.f, ps1 = 0.f;
        #pragma unroll
        for (int nt = 0; nt < 4; nt++) {
            p[nt][0] = __expf(accS[nt][0] - mt0);
            p[nt][1] = __expf(accS[nt][1] - mt0);
            p[nt][2] = __expf(accS[nt][2] - mt1);
            p[nt][3] = __expf(accS[nt][3] - mt1);
            ps0 += p[nt][0] + p[nt][1];
            ps1 += p[nt][2] + p[nt][3];
        }
        ps0 += __shfl_xor_sync(0xffffffffu, ps0, 1);
        ps0 += __shfl_xor_sync(0xffffffffu, ps0, 2);
        ps1 += __shfl_xor_sync(0xffffffffu, ps1, 1);
        ps1 += __shfl_xor_sync(0xffffffffu, ps1, 2);
        l0 = l0 * alpha0 + ps0;
        l1 = l1 * alpha1 + ps1;

        #pragma unroll
        for (int i = 0; i < 16; i++) {
            accO[i][0] *= alpha0; accO[i][1] *= alpha0;
            accO[i][2] *= alpha1; accO[i][3] *= alpha1;
        }

        uint32_t ph[2][4], pl[2][4];
        #pragma unroll
        for (int kb = 0; kb < 2; kb++) {
            #pragma unroll
            for (int q = 0; q < 4; q++) {
                int nt = 2*kb + (q >> 1);
                int e0 = (q & 1) * 2;
                float v0 = p[nt][e0], v1 = p[nt][e0 + 1];
                __half h0 = __float2half(v0), h1 = __float2half(v1);
                __half lo0 = __float2half(v0 - __half2float(h0));
                __half lo1 = __float2half(v1 - __half2float(h1));
                int ridx = (q >> 1) * 2 + (q & 1);
                __half2 hh = __halves2half2(h0, h1);
                __half2 ll = __halves2half2(lo0, lo1);
                ph[kb][ridx] = *(uint32_t*)&hh;
                pl[kb][ridx] = *(uint32_t*)&ll;
            }
        }

        #pragma unroll
        for (int kb = 0; kb < 2; kb++) {
            #pragma unroll
            for (int dg = 0; dg < 8; dg++) {
                uint32_t vb[4], vbl[4];
                uint32_t voff = vt_off + (uint32_t)((kb * 16 * ASTR + dg * 16) * 2);
                ldsm_x4_t(vb,  vh_b + voff);
                ldsm_x4_t(vbl, vl_b + voff);
                mma_fp16(accO[2*dg],     ph[kb], &vb[0]);
                mma_fp16(accO[2*dg],     pl[kb], &vb[0]);
                mma_fp16(accO[2*dg],     ph[kb], &vbl[0]);
                mma_fp16(accO[2*dg + 1], ph[kb], &vb[2]);
                mma_fp16(accO[2*dg + 1], pl[kb], &vb[2]);
                mma_fp16(accO[2*dg + 1], ph[kb], &vbl[2]);
            }
        }
    }

    float li0 = 1.0f / l0, li1 = 1.0f / l1;
    size_t ob0 = (size_t)(b * SEQ + i0 + w*16 + g) * H_SIZE + h * HD;
    size_t ob1 = ob0 + (size_t)8 * H_SIZE;
    #pragma unroll
    for (int nt = 0; nt < 16; nt++) {
        int dim = nt * 8 + 2 * t;
        split2h(accO[nt][0] * li0, accO[nt][1] * li0, Oh + ob0 + dim, Ol + ob0 + dim);
        split2h(accO[nt][2] * li1, accO[nt][3] * li1, Oh + ob1 + dim, Ol + ob1 + dim);
    }
}

// ---------------- GeGLU: fp16 hi plane out ----------------
__device__ __forceinline__ float gelu_exact(float x) {
    return 0.5f * x * (1.0f + erff(x * 0.7071067811865476f));
}
__global__ __launch_bounds__(256) void geglu_kernel(
    const float* __restrict__ g, const float* __restrict__ u,
    __half* __restrict__ oh, int n4)
{
    int i = blockIdx.x * blockDim.x + threadIdx.x;
    int stride = gridDim.x * blockDim.x;
    for (; i < n4; i += stride) {
        float4 gv = ((const float4*)g)[i];
        float4 uv = ((const float4*)u)[i];
        float r0 = gelu_exact(gv.x) * uv.x;
        float r1 = gelu_exact(gv.y) * uv.y;
        float r2 = gelu_exact(gv.z) * uv.z;
        float r3 = gelu_exact(gv.w) * uv.w;
        *(__half2*)(oh + i*4)     = __halves2half2(__float2half(r0), __float2half(r1));
        *(__half2*)(oh + i*4 + 2) = __halves2half2(__float2half(r2), __float2half(r3));
    }
}

// ---------------- launch ----------------
extern "C" void kernel_launch(void* const* d_in, const int* in_sizes, int n_in,
                              void* d_out, int out_size)
{
    const float* x    = (const float*)d_in[0];
    const float* wq   = (const float*)d_in[1];
    const float* wk   = (const float*)d_in[2];
    const float* wv   = (const float*)d_in[3];
    const float* wo   = (const float*)d_in[4];
    const float* w_in = (const float*)d_in[5];
    const float* w_pa = (const float*)d_in[6];
    const float* w_pf = (const float*)d_in[7];
    const float* w_pff= (const float*)d_in[8];
    const float* wg   = (const float*)d_in[9];
    const float* wu   = (const float*)d_in[10];
    const float* wd   = (const float*)d_in[11];
    const float* lsc  = (const float*)d_in[12];
    float* out = (float*)d_out;

    float *q, *k, *v, *attnout, *h2, *gate, *up, *ffnout;
    cudaGetSymbolAddress((void**)&q,       g_q);
    cudaGetSymbolAddress((void**)&k,       g_k);
    cudaGetSymbolAddress((void**)&v,       g_v);
    cudaGetSymbolAddress((void**)&attnout, g_attnout);
    cudaGetSymbolAddress((void**)&h2,      g_h2);
    cudaGetSymbolAddress((void**)&gate,    g_gate);
    cudaGetSymbolAddress((void**)&up,      g_up);
    cudaGetSymbolAddress((void**)&ffnout,  g_ffnout);

    __half *h_h, *h_l, *attn_h, *attn_l, *ffnin_h, *ffnin_l, *gact_h;
    __half *pwq, *pwk, *pwv, *pwo, *pwg, *pwu, *pwd;
    cudaGetSymbolAddress((void**)&h_h, g_h_h);         cudaGetSymbolAddress((void**)&h_l, g_h_l);
    cudaGetSymbolAddress((void**)&attn_h, g_attn_h);   cudaGetSymbolAddress((void**)&attn_l, g_attn_l);
    cudaGetSymbolAddress((void**)&ffnin_h, g_ffnin_h); cudaGetSymbolAddress((void**)&ffnin_l, g_ffnin_l);
    cudaGetSymbolAddress((void**)&gact_h, g_gact_h);
    cudaGetSymbolAddress((void**)&pwq, g_wq);
    cudaGetSymbolAddress((void**)&pwk, g_wk);
    cudaGetSymbolAddress((void**)&pwv, g_wv);
    cudaGetSymbolAddress((void**)&pwo, g_wo);
    cudaGetSymbolAddress((void**)&pwg, g_wg);
    cudaGetSymbolAddress((void**)&pwu, g_wu);
    cudaGetSymbolAddress((void**)&pwd, g_wd);

    const int smem2 = 2 * (2*A_PLANE + B_PLANE) * 2;
    const int smem1 = 2 * (A_PLANE + B_PLANE) * 2;
    cudaFuncSetAttribute(attn_mma_kernel, cudaFuncAttributeMaxDynamicSharedMemorySize, ATTN2_SMEM);
    cudaFuncSetAttribute(gemm_mma<true>,  cudaFuncAttributeMaxDynamicSharedMemorySize, smem2);
    cudaFuncSetAttribute(gemm_mma<false>, cudaFuncAttributeMaxDynamicSharedMemorySize, smem1);

    // weight planes (fp16)
    wsplit_kernel<<<2048, 256>>>(wq, pwq, H_SIZE*H_SIZE/4);
    wsplit_kernel<<<1024, 256>>>(wk, pwk, NKV*HD*H_SIZE/4);
    wsplit_kernel<<<1024, 256>>>(wv, pwv, NKV*HD*H_SIZE/4);
    wsplit_kernel<<<2048, 256>>>(wo, pwo, H_SIZE*H_SIZE/4);
    wsplit_kernel<<<4096, 256>>>(wg, pwg, INTER_SZ*H_SIZE/4);
    wsplit_kernel<<<4096, 256>>>(wu, pwu, INTER_SZ*H_SIZE/4);
    wsplit_kernel<<<4096, 256>>>(wd, pwd, H_SIZE*INTER_SZ/4);

    // h = rmsnorm(x, w_in) -> fp16 hi/lo planes
    rmsnorm_split_kernel<<<NROWS, 256>>>(x, w_in, h_h, h_l);
    // QKV (2-pass)
    gemm_mma<true><<<dim3(H_SIZE/128, NROWS/256), 256, smem2>>>(h_h, h_l, pwq, q, NROWS, H_SIZE, H_SIZE);
    gemm_mma<true><<<dim3((NKV*HD)/128, NROWS/256), 256, smem2>>>(h_h, h_l, pwk, k, NROWS, NKV*HD, H_SIZE);
    gemm_mma<true><<<dim3((NKV*HD)/128, NROWS/256), 256, smem2>>>(h_h, h_l, pwv, v, NROWS, NKV*HD, H_SIZE);
    // RoPE
    rope_kernel<<<NROWS, 256>>>(q, NQ);
    rope_kernel<<<NROWS, 256>>>(k, NKV);
    // tensor-core attention -> fp16 planes
    attn_mma_kernel<<<dim3(SEQ/128, NQ, BATCH), 256, ATTN2_SMEM>>>(q, k, v, attn_h, attn_l);
    // WO (2-pass)
    gemm_mma<true><<<dim3(H_SIZE/128, NROWS/256), 256, smem2>>>(attn_h, attn_l, pwo, attnout, NROWS, H_SIZE, H_SIZE);
    // h2 = x + rmsnorm(attnout, w_pa)
    rmsnorm_kernel<<<NROWS, 256>>>(attnout, w_pa, x, nullptr, h2, 1);
    // ffn_in = rmsnorm(h2, w_pf) -> fp16 planes
    rmsnorm_split_kernel<<<NROWS, 256>>>(h2, w_pf, ffnin_h, ffnin_l);
    // gate/up GEMMs (1-pass fp16)
    gemm_mma<false><<<dim3(INTER_SZ/128, NROWS/256), 256, smem1>>>(ffnin_h, nullptr, pwg, gate, NROWS, INTER_SZ, H_SIZE);
    gemm_mma<false><<<dim3(INTER_SZ/128, NROWS/256), 256, smem1>>>(ffnin_h, nullptr, pwu, up, NROWS, INTER_SZ, H_SIZE);
    // act = gelu(gate) * up -> fp16 hi plane
    geglu_kernel<<<8192, 256>>>(gate, up, gact_h, (NROWS * INTER_SZ) / 4);
    // down projection (1-pass fp16, K = INTER)
    gemm_mma<false><<<dim3(H_SIZE/128, NROWS/256), 256, smem1>>>(gact_h, nullptr, pwd, ffnout, NROWS, H_SIZE, INTER_SZ);
    // out = (h2 + rmsnorm(ffnout, w_pff)) * layer_scalar
    rmsnorm_kernel<<<NROWS, 256>>>(ffnout, w_pff, h2, lsc, out, 2);
}

// round 16
// speedup vs baseline: 1.0640x; 1.0627x over previous
#include <cuda_runtime.h>
#include <cuda_fp16.h>
#include <stdint.h>
#include <math.h>

#define H_SIZE 2048
#define INTER_SZ 8192
#define NQ 16
#define NKV 8
#define HD 128
#define SEQ 2048
#define BATCH 2
#define NROWS (BATCH*SEQ)
#define WIN 1024

// ---------------- fp32 scratch ----------------
__device__ float g_q[NROWS*H_SIZE];
__device__ float g_k[NROWS*NKV*HD];
__device__ float g_v[NROWS*NKV*HD];
__device__ float g_attnout[NROWS*H_SIZE];
__device__ float g_h2[NROWS*H_SIZE];
__device__ float g_gate[NROWS*INTER_SZ];
__device__ float g_up[NROWS*INTER_SZ];
__device__ float g_ffnout[NROWS*H_SIZE];

// ---------------- fp16 planes ----------------
__device__ __half g_h_h[NROWS*H_SIZE],      g_h_l[NROWS*H_SIZE];
__device__ __half g_attn_h[NROWS*H_SIZE],   g_attn_l[NROWS*H_SIZE];
__device__ __half g_ffnin_h[NROWS*H_SIZE],  g_ffnin_l[NROWS*H_SIZE];
__device__ __half g_gact_h[NROWS*INTER_SZ];
__device__ __half g_wq[H_SIZE*H_SIZE];
__device__ __half g_wk[NKV*HD*H_SIZE];
__device__ __half g_wv[NKV*HD*H_SIZE];
__device__ __half g_wo[H_SIZE*H_SIZE];
__device__ __half g_wg[INTER_SZ*H_SIZE];
__device__ __half g_wu[INTER_SZ*H_SIZE];
__device__ __half g_wd[H_SIZE*INTER_SZ];

// ---------------- helpers ----------------
__device__ __forceinline__ void split2h(float a, float b, __half* hi, __half* lo) {
    __half ha = __float2half(a), hb = __float2half(b);
    __half la = __float2half(a - __half2float(ha));
    __half lb = __float2half(b - __half2float(hb));
    *(__half2*)hi = __halves2half2(ha, hb);
    *(__half2*)lo = __halves2half2(la, lb);
}

__global__ __launch_bounds__(256) void wsplit_kernel(
    const float* __restrict__ in, __half* __restrict__ out, int n4)
{
    int i = blockIdx.x * blockDim.x + threadIdx.x;
    int stride = gridDim.x * blockDim.x;
    for (; i < n4; i += stride) {
        float4 v = ((const float4*)in)[i];
        *(__half2*)(out + i*4)     = __halves2half2(__float2half(v.x), __float2half(v.y));
        *(__half2*)(out + i*4 + 2) = __halves2half2(__float2half(v.z), __float2half(v.w));
    }
}

// ---------------- RMSNorm fp32 out ----------------
__global__ __launch_bounds__(256) void rmsnorm_kernel(
    const float* __restrict__ in, const float* __restrict__ w,
    const float* __restrict__ res, const float* __restrict__ scal,
    float* __restrict__ out, int mode)
{
    int row = blockIdx.x;
    int t = threadIdx.x;
    const float4* ip = (const float4*)(in + (size_t)row * H_SIZE);
    float4 v0 = ip[t];
    float4 v1 = ip[t + 256];
    float ss = v0.x*v0.x + v0.y*v0.y + v0.z*v0.z + v0.w*v0.w
             + v1.x*v1.x + v1.y*v1.y + v1.z*v1.z + v1.w*v1.w;
    #pragma unroll
    for (int o = 16; o; o >>= 1) ss += __shfl_xor_sync(0xffffffffu, ss, o);
    __shared__ float red[8];
    if ((t & 31) == 0) red[t >> 5] = ss;
    __syncthreads();
    float tot = red[0]+red[1]+red[2]+red[3]+red[4]+red[5]+red[6]+red[7];
    float inv = rsqrtf(tot * (1.0f / H_SIZE) + 1e-6f);

    const float4* w4 = (const float4*)w;
    float4 w0 = w4[t], w1 = w4[t + 256];
    float4 o0, o1;
    o0.x = v0.x*inv*w0.x; o0.y = v0.y*inv*w0.y; o0.z = v0.z*inv*w0.z; o0.w = v0.w*inv*w0.w;
    o1.x = v1.x*inv*w1.x; o1.y = v1.y*inv*w1.y; o1.z = v1.z*inv*w1.z; o1.w = v1.w*inv*w1.w;
    if (mode >= 1) {
        const float4* rp = (const float4*)(res + (size_t)row * H_SIZE);
        float4 r0 = rp[t], r1 = rp[t + 256];
        o0.x += r0.x; o0.y += r0.y; o0.z += r0.z; o0.w += r0.w;
        o1.x += r1.x; o1.y += r1.y; o1.z += r1.z; o1.w += r1.w;
    }
    if (mode == 2) {
        float sc = scal[0];
        o0.x *= sc; o0.y *= sc; o0.z *= sc; o0.w *= sc;
        o1.x *= sc; o1.y *= sc; o1.z *= sc; o1.w *= sc;
    }
    float4* op = (float4*)(out + (size_t)row * H_SIZE);
    op[t] = o0;
    op[t + 256] = o1;
}

// ---------------- RMSNorm -> fp16 hi/lo planes ----------------
__global__ __launch_bounds__(256) void rmsnorm_split_kernel(
    const float* __restrict__ in, const float* __restrict__ w,
    __half* __restrict__ oh, __half* __restrict__ ol)
{
    int row = blockIdx.x;
    int t = threadIdx.x;
    const float4* ip = (const float4*)(in + (size_t)row * H_SIZE);
    float4 v0 = ip[t];
    float4 v1 = ip[t + 256];
    float ss = v0.x*v0.x + v0.y*v0.y + v0.z*v0.z + v0.w*v0.w
             + v1.x*v1.x + v1.y*v1.y + v1.z*v1.z + v1.w*v1.w;
    #pragma unroll
    for (int o = 16; o; o >>= 1) ss += __shfl_xor_sync(0xffffffffu, ss, o);
    __shared__ float red[8];
    if ((t & 31) == 0) red[t >> 5] = ss;
    __syncthreads();
    float tot = red[0]+red[1]+red[2]+red[3]+red[4]+red[5]+red[6]+red[7];
    float inv = rsqrtf(tot * (1.0f / H_SIZE) + 1e-6f);

    const float4* w4 = (const float4*)w;
    float4 w0 = w4[t], w1 = w4[t + 256];
    size_t base = (size_t)row * H_SIZE;
    split2h(v0.x*inv*w0.x, v0.y*inv*w0.y, oh + base + t*4,     ol + base + t*4);
    split2h(v0.z*inv*w0.z, v0.w*inv*w0.w, oh + base + t*4 + 2, ol + base + t*4 + 2);
    split2h(v1.x*inv*w1.x, v1.y*inv*w1.y, oh + base + 1024 + t*4,     ol + base + 1024 + t*4);
    split2h(v1.z*inv*w1.z, v1.w*inv*w1.w, oh + base + 1024 + t*4 + 2, ol + base + 1024 + t*4 + 2);
}

// ---------------- MMA helpers ----------------
__device__ __forceinline__ void mma_fp16(float* c, const uint32_t* a, const uint32_t* b) {
    asm volatile(
        "mma.sync.aligned.m16n8k16.row.col.f32.f16.f16.f32 "
        "{%0,%1,%2,%3}, {%4,%5,%6,%7}, {%8,%9}, {%0,%1,%2,%3};\n"
        : "+f"(c[0]), "+f"(c[1]), "+f"(c[2]), "+f"(c[3])
        : "r"(a[0]), "r"(a[1]), "r"(a[2]), "r"(a[3]), "r"(b[0]), "r"(b[1]));
}

__device__ __forceinline__ void ldsm_x4(uint32_t* r, uint32_t addr) {
    asm volatile("ldmatrix.sync.aligned.m8n8.x4.shared.b16 {%0,%1,%2,%3}, [%4];"
        : "=r"(r[0]), "=r"(r[1]), "=r"(r[2]), "=r"(r[3]) : "r"(addr));
}

__device__ __forceinline__ void ldsm_x4_t(uint32_t* r, uint32_t addr) {
    asm volatile("ldmatrix.sync.aligned.m8n8.x4.trans.shared.b16 {%0,%1,%2,%3}, [%4];"
        : "=r"(r[0]), "=r"(r[1]), "=r"(r[2]), "=r"(r[3]) : "r"(addr));
}

__device__ __forceinline__ void cp16(uint32_t dst, const void* src) {
    asm volatile("cp.async.cg.shared.global [%0], [%1], 16;\n" :: "r"(dst), "l"(src));
}

// ---------------- Tensor-core GEMM (R13 geometry): block 128x128, warp tile 32x64 --------
// 2 CTAs/SM. TWOPASS: 3 planes, 2-stage pipeline. 1-pass: 2 planes, 3-stage pipeline.
// plane order in stage: [0]=Ah, [1]=Bh, [2]=Al(TWOPASS only)

#define LDSK 40
#define PLANE_H (128*LDSK)

template<bool TWOPASS>
__global__ __launch_bounds__(256, 2) void gemm_mma(
    const __half* __restrict__ Agh, const __half* __restrict__ Agl,
    const __half* __restrict__ Bgh,
    float* __restrict__ C, int M, int N, int K)
{
    extern __shared__ __align__(16) __half smp[];
    const int NPL = TWOPASS ? 3 : 2;
    const int NSTAGE = TWOPASS ? 2 : 3;
    const int STAGE_HH = NPL * PLANE_H;

    const int tid  = threadIdx.x;
    const int warp = tid >> 5, lane = tid & 31;
    const int wm = warp >> 1, wn = warp & 1;   // 4 x 2 warp grid, warp tile 32x64
    const int rowA = blockIdx.y * 128;
    const int colB = blockIdx.x * 128;

    const uint32_t smb = (uint32_t)__cvta_generic_to_shared(smp);
    const uint32_t a_off = (uint32_t)(((wm*32 + (lane & 15)) * LDSK + ((lane >> 4) * 8)) * 2);
    const uint32_t b_off = (uint32_t)(((wn*64 + ((lane >> 4) * 8) + (lane & 7)) * LDSK
                                       + (((lane >> 3) & 1) * 8)) * 2);

    float acc[2][8][4];
    #pragma unroll
    for (int i = 0; i < 2; i++)
        #pragma unroll
        for (int j = 0; j < 8; j++)
            #pragma unroll
            for (int q = 0; q < 4; q++) acc[i][j][q] = 0.f;

    #define CP_STAGE(s, k0)                                                        \
    {                                                                              \
        _Pragma("unroll")                                                          \
        for (int i = 0; i < 2*NPL; i++) {                                          \
            int cidx = tid + 256 * i;                                              \
            int plane = cidx >> 9;                                                 \
            int cc = cidx & 511;                                                   \
            int row = cc >> 2;                                                     \
            int ch = cc & 3;                                                       \
            const __half* src =                                                    \
                (plane == 0) ? Agh + (size_t)(rowA + row) * K :                    \
                (plane == 1) ? Bgh + (size_t)(colB + row) * K :                    \
                               Agl + (size_t)(rowA + row) * K;                     \
            uint32_t dst = smb +                                                   \
                (uint32_t)(((s) * STAGE_HH + plane * PLANE_H + row * LDSK + ch * 8) * 2); \
            cp16(dst, src + (k0) + ch * 8);                                        \
        }                                                                          \
        asm volatile("cp.async.commit_group;\n" ::: "memory");                     \
    }

    const int NC = K >> 5;
    // prologue: fill NSTAGE-1 stages
    CP_STAGE(0, 0);
    if (NSTAGE == 3 && NC > 1) CP_STAGE(1, 32);

    for (int c = 0; c < NC; c++) {
        int s = c % NSTAGE;
        int nf = c + NSTAGE - 1;          // next stage to fetch
        if (nf < NC) {
            CP_STAGE(nf % NSTAGE, nf * 32);
            if (TWOPASS) asm volatile("cp.async.wait_group 1;\n" ::: "memory");
            else         asm volatile("cp.async.wait_group 2;\n" ::: "memory");
        } else {
            int rem = NC - 1 - c;         // groups still in flight beyond stage c
            if (rem >= 1) asm volatile("cp.async.wait_group 1;\n" ::: "memory");
            else          asm volatile("cp.async.wait_group 0;\n" ::: "memory");
        }
        __syncthreads();

        const uint32_t ah_b = smb + (uint32_t)((s * STAGE_HH) * 2);
        const uint32_t bh_b = ah_b + (uint32_t)(PLANE_H * 2);
        const uint32_t al_b = bh_b + (uint32_t)(PLANE_H * 2);

        #pragma unroll
        for (int kk = 0; kk < 32; kk += 16) {
            const uint32_t kko = kk * 2;
            uint32_t fa[2][4];
            uint32_t fb[4][4];
            #pragma unroll
            for (int tm = 0; tm < 2; tm++)
                ldsm_x4(fa[tm], ah_b + a_off + (uint32_t)(tm * 16 * LDSK * 2) + kko);
            #pragma unroll
            for (int p = 0; p < 4; p++)
                ldsm_x4(fb[p], bh_b + b_off + (uint32_t)(p * 16 * LDSK * 2) + kko);
            #pragma unroll
            for (int tm = 0; tm < 2; tm++)
                #pragma unroll
                for (int tn = 0; tn < 8; tn++)
                    mma_fp16(acc[tm][tn], fa[tm], &fb[tn >> 1][(tn & 1) * 2]);
            if (TWOPASS) {
                uint32_t fal[2][4];
                #pragma unroll
                for (int tm = 0; tm < 2; tm++)
                    ldsm_x4(fal[tm], al_b + a_off + (uint32_t)(tm * 16 * LDSK * 2) + kko);
                #pragma unroll
                for (int tm = 0; tm < 2; tm++)
                    #pragma unroll
                    for (int tn = 0; tn < 8; tn++)
                        mma_fp16(acc[tm][tn], fal[tm], &fb[tn >> 1][(tn & 1) * 2]);
            }
        }
        __syncthreads();
    }

    const int g = lane >> 2, t4 = lane & 3;
    #pragma unroll
    for (int tm = 0; tm < 2; tm++) {
        #pragma unroll
        for (int tn = 0; tn < 8; tn++) {
            int row = blockIdx.y*128 + wm*32 + tm*16 + g;
            int col = blockIdx.x*128 + wn*64 + tn*8 + 2*t4;
            float2 c0 = {acc[tm][tn][0], acc[tm][tn][1]};
            float2 c1 = {acc[tm][tn][2], acc[tm][tn][3]};
            *(float2*)(C + (size_t)row * N + col)       = c0;
            *(float2*)(C + (size_t)(row + 8) * N + col) = c1;
        }
    }
}

// ---------------- RoPE ----------------
__global__ __launch_bounds__(256) void rope_kernel(float* __restrict__ buf, int nheads)
{
    int row = blockIdx.x;
    int s = row & (SEQ - 1);
    float* base = buf + (size_t)row * nheads * HD;
    for (int idx = threadIdx.x; idx < nheads * 64; idx += blockDim.x) {
        int hh = idx >> 6;
        int d = idx & 63;
        float inv = expf(-((float)d * (1.0f / 64.0f)) * 9.210340371976184f);
        float fr = (float)s * inv;
        float sn = sinf(fr), cs = cosf(fr);
        float* p = base + hh * HD + d;
        float x1 = p[0], x2 = p[64];
        p[0]  = x1 * cs - x2 * sn;
        p[64] = x2 * cs + x1 * sn;
    }
}

// ---------------- Tensor-core sliding-window GQA flash attention (R13) -------------------
#define ASTR 136
#define ATTN2_SMEM ((128*ASTR*2 + 32*ASTR*4) * 2)

__global__ __launch_bounds__(256) void attn_mma_kernel(
    const float* __restrict__ Q, const float* __restrict__ K,
    const float* __restrict__ V, __half* __restrict__ Oh,
    __half* __restrict__ Ol)
{
    extern __shared__ __align__(16) __half asmem[];
    __half* Qh = asmem;
    __half* Ql = Qh + 128*ASTR;
    __half* Kh = Ql + 128*ASTR;
    __half* Kl = Kh + 32*ASTR;
    __half* Vh = Kl + 32*ASTR;
    __half* Vl = Vh + 32*ASTR;

    const int i0 = blockIdx.x * 128;
    const int h  = blockIdx.y;
    const int b  = blockIdx.z;
    const int hk = h >> 1;
    const int tid = threadIdx.x;
    const int w = tid >> 5, lane = tid & 31;
    const int g = lane >> 2, t = lane & 3;
    const float scale = 0.08838834764831845f;

    const uint32_t qh_b = (uint32_t)__cvta_generic_to_shared(Qh);
    const uint32_t ql_b = (uint32_t)__cvta_generic_to_shared(Ql);
    const uint32_t kh_b = (uint32_t)__cvta_generic_to_shared(Kh);
    const uint32_t kl_b = (uint32_t)__cvta_generic_to_shared(Kl);
    const uint32_t vh_b = (uint32_t)__cvta_generic_to_shared(Vh);
    const uint32_t vl_b = (uint32_t)__cvta_generic_to_shared(Vl);

    const uint32_t a_off  = (uint32_t)(((w*16 + (lane & 15)) * ASTR + ((lane >> 4) * 8)) * 2);
    const uint32_t kb_off = (uint32_t)((((lane >> 4) * 8 + (lane & 7)) * ASTR
                                        + ((lane >> 3) & 1) * 8) * 2);
    const uint32_t vt_off = (uint32_t)((((lane & 7) + 8 * ((lane >> 3) & 1)) * ASTR
                                        + 8 * (lane >> 4)) * 2);

    #pragma unroll
    for (int it = 0; it < 16; it++) {
        int idx = tid + 256 * it;
        int row = idx >> 5, d4 = idx & 31;
        float4 qv = *(const float4*)(Q + (size_t)(b * SEQ + i0 + row) * H_SIZE + h * HD + d4 * 4);
        int off = row * ASTR + d4 * 4;
        split2h(qv.x * scale, qv.y * scale, Qh + off,     Ql + off);
        split2h(qv.z * scale, qv.w * scale, Qh + off + 2, Ql + off + 2);
    }

    float accO[16][4];
    #pragma unroll
    for (int i = 0; i < 16; i++)
        #pragma unroll
        for (int q = 0; q < 4; q++) accO[i][q] = 0.f;
    float m0 = -1e30f, m1 = -1e30f, l0 = 0.f, l1 = 0.f;

    int jstart = i0 - (WIN - 1);
    if (jstart < 0) jstart = 0;
    jstart &= ~31;
    const int r0 = i0 + w*16 + g;
    const int r1 = r0 + 8;

    for (int j0 = jstart; j0 < i0 + 128; j0 += 32) {
        __syncthreads();
        #pragma unroll
        for (int it = 0; it < 4; it++) {
            int idx = tid + 256 * it;
            int row = idx >> 5, d4 = idx & 31;
            size_t goff = (size_t)(b * SEQ + j0 + row) * (NKV * HD) + hk * HD + d4 * 4;
            float4 kv = *(const float4*)(K + goff);
            float4 vv = *(const float4*)(V + goff);
            int off = row * ASTR + d4 * 4;
            split2h(kv.x, kv.y, Kh + off,     Kl + off);
            split2h(kv.z, kv.w, Kh + off + 2, Kl + off + 2);
            split2h(vv.x, vv.y, Vh + off,     Vl + off);
            split2h(vv.z, vv.w, Vh + off + 2, Vl + off + 2);
        }
        __syncthreads();

        float accS[4][4];
        #pragma unroll
        for (int nt = 0; nt < 4; nt++)
            #pragma unroll
            for (int q = 0; q < 4; q++) accS[nt][q] = 0.f;

        #pragma unroll
        for (int ks = 0; ks < 8; ks++) {
            const uint32_t kko = (uint32_t)(ks * 32);
            uint32_t fa[4], fal[4], fb[2][4], fbl[2][4];
            ldsm_x4(fa,  qh_b + a_off + kko);
            ldsm_x4(fal, ql_b + a_off + kko);
            ldsm_x4(fb[0],  kh_b + kb_off + kko);
            ldsm_x4(fb[1],  kh_b + kb_off + (uint32_t)(16 * ASTR * 2) + kko);
            ldsm_x4(fbl[0], kl_b + kb_off + kko);
            ldsm_x4(fbl[1], kl_b + kb_off + (uint32_t)(16 * ASTR * 2) + kko);
            #pragma unroll
            for (int nt = 0; nt < 4; nt++) {
                mma_fp16(accS[nt], fa,  &fb[nt >> 1][(nt & 1) * 2]);
                mma_fp16(accS[nt], fal, &fb[nt >> 1][(nt & 1) * 2]);
                mma_fp16(accS[nt], fa,  &fbl[nt >> 1][(nt & 1) * 2]);
            }
        }

        #pragma unroll
        for (int nt = 0; nt < 4; nt++) {
            int jc0 = j0 + nt * 8 + 2 * t;
            int jc1 = jc0 + 1;
            accS[nt][0] = (jc0 <= r0 && r0 - jc0 < WIN) ? accS[nt][0] : -1e30f;
            accS[nt][1] = (jc1 <= r0 && r0 - jc1 < WIN) ? accS[nt][1] : -1e30f;
            accS[nt][2] = (jc0 <= r1 && r1 - jc0 < WIN) ? accS[nt][2] : -1e30f;
            accS[nt][3] = (jc1 <= r1 && r1 - jc1 < WIN) ? accS[nt][3] : -1e30f;
        }

        float mt0 = m0, mt1 = m1;
        #pragma unroll
        for (int nt = 0; nt < 4; nt++) {
            mt0 = fmaxf(mt0, fmaxf(accS[nt][0], accS[nt][1]));
            mt1 = fmaxf(mt1, fmaxf(accS[nt][2], accS[nt][3]));
        }
        mt0 = fmaxf(mt0, __shfl_xor_sync(0xffffffffu, mt0, 1));
        mt0 = fmaxf(mt0, __shfl_xor_sync(0xffffffffu, mt0, 2));
        mt1 = fmaxf(mt1, __shfl_xor_sync(0xffffffffu, mt1, 1));
        mt1 = fmaxf(mt1, __shfl_xor_sync(0xffffffffu, mt1, 2));
        float alpha0 = __expf(m0 - mt0);
        float alpha1 = __expf(m1 - mt1);
        m0 = mt0; m1 = mt1;

        float p[4][4];
        float ps0 = 0.f, ps1 = 0.f;
        #pragma unroll
        for (int nt = 0; nt < 4; nt++) {
            p[nt][0] = __expf(accS[nt][0] - mt0);
            p[nt][1] = __expf(accS[nt][1] - mt0);
            p[nt][2] = __expf(accS[nt][2] - mt1);
            p[nt][3] = __expf(accS[nt][3] - mt1);
            ps0 += p[nt][0] + p[nt][1];
            ps1 += p[nt][2] + p[nt][3];
        }
        ps0 += __shfl_xor_sync(0xffffffffu, ps0, 1);
        ps0 += __shfl_xor_sync(0xffffffffu, ps0, 2);
        ps1 += __shfl_xor_sync(0xffffffffu, ps1, 1);
        ps1 += __shfl_xor_sync(0xffffffffu, ps1, 2);
        l0 = l0 * alpha0 + ps0;
        l1 = l1 * alpha1 + ps1;

        #pragma unroll
        for (int i = 0; i < 16; i++) {
            accO[i][0] *= alpha0; accO[i][1] *= alpha0;
            accO[i][2] *= alpha1; accO[i][3] *= alpha1;
        }

        uint32_t ph[2][4], pl[2][4];
        #pragma unroll
        for (int kb = 0; kb < 2; kb++) {
            #pragma unroll
            for (int q = 0; q < 4; q++) {
                int nt = 2*kb + (q >> 1);
                int e0 = (q & 1) * 2;
                float v0 = p[nt][e0], v1 = p[nt][e0 + 1];
                __half h0 = __float2half(v0), h1 = __float2half(v1);
                __half lo0 = __float2half(v0 - __half2float(h0));
                __half lo1 = __float2half(v1 - __half2float(h1));
                int ridx = (q >> 1) * 2 + (q & 1);
                __half2 hh = __halves2half2(h0, h1);
                __half2 ll = __halves2half2(lo0, lo1);
                ph[kb][ridx] = *(uint32_t*)&hh;
                pl[kb][ridx] = *(uint32_t*)&ll;
            }
        }

        #pragma unroll
        for (int kb = 0; kb < 2; kb++) {
            #pragma unroll
            for (int dg = 0; dg < 8; dg++) {
                uint32_t vb[4], vbl[4];
                uint32_t voff = vt_off + (uint32_t)((kb * 16 * ASTR + dg * 16) * 2);
                ldsm_x4_t(vb,  vh_b + voff);
                ldsm_x4_t(vbl, vl_b + voff);
                mma_fp16(accO[2*dg],     ph[kb], &vb[0]);
                mma_fp16(accO[2*dg],     pl[kb], &vb[0]);
                mma_fp16(accO[2*dg],     ph[kb], &vbl[0]);
                mma_fp16(accO[2*dg + 1], ph[kb], &vb[2]);
                mma_fp16(accO[2*dg + 1], pl[kb], &vb[2]);
                mma_fp16(accO[2*dg + 1], ph[kb], &vbl[2]);
            }
        }
    }

    float li0 = 1.0f / l0, li1 = 1.0f / l1;
    size_t ob0 = (size_t)(b * SEQ + i0 + w*16 + g) * H_SIZE + h * HD;
    size_t ob1 = ob0 + (size_t)8 * H_SIZE;
    #pragma unroll
    for (int nt = 0; nt < 16; nt++) {
        int dim = nt * 8 + 2 * t;
        split2h(accO[nt][0] * li0, accO[nt][1] * li0, Oh + ob0 + dim, Ol + ob0 + dim);
        split2h(accO[nt][2] * li1, accO[nt][3] * li1, Oh + ob1 + dim, Ol + ob1 + dim);
    }
}

// ---------------- GeGLU: fp16 hi plane out ----------------
__device__ __forceinline__ float gelu_exact(float x) {
    return 0.5f * x * (1.0f + erff(x * 0.7071067811865476f));
}
__global__ __launch_bounds__(256) void geglu_kernel(
    const float* __restrict__ g, const float* __restrict__ u,
    __half* __restrict__ oh, int n4)
{
    int i = blockIdx.x * blockDim.x + threadIdx.x;
    int stride = gridDim.x * blockDim.x;
    for (; i < n4; i += stride) {
        float4 gv = ((const float4*)g)[i];
        float4 uv = ((const float4*)u)[i];
        float r0 = gelu_exact(gv.x) * uv.x;
        float r1 = gelu_exact(gv.y) * uv.y;
        float r2 = gelu_exact(gv.z) * uv.z;
        float r3 = gelu_exact(gv.w) * uv.w;
        *(__half2*)(oh + i*4)     = __halves2half2(__float2half(r0), __float2half(r1));
        *(__half2*)(oh + i*4 + 2) = __halves2half2(__float2half(r2), __float2half(r3));
    }
}

// ---------------- launch ----------------
extern "C" void kernel_launch(void* const* d_in, const int* in_sizes, int n_in,
                              void* d_out, int out_size)
{
    const float* x    = (const float*)d_in[0];
    const float* wq   = (const float*)d_in[1];
    const float* wk   = (const float*)d_in[2];
    const float* wv   = (const float*)d_in[3];
    const float* wo   = (const float*)d_in[4];
    const float* w_in = (const float*)d_in[5];
    const float* w_pa = (const float*)d_in[6];
    const float* w_pf = (const float*)d_in[7];
    const float* w_pff= (const float*)d_in[8];
    const float* wg   = (const float*)d_in[9];
    const float* wu   = (const float*)d_in[10];
    const float* wd   = (const float*)d_in[11];
    const float* lsc  = (const float*)d_in[12];
    float* out = (float*)d_out;

    float *q, *k, *v, *attnout, *h2, *gate, *up, *ffnout;
    cudaGetSymbolAddress((void**)&q,       g_q);
    cudaGetSymbolAddress((void**)&k,       g_k);
    cudaGetSymbolAddress((void**)&v,       g_v);
    cudaGetSymbolAddress((void**)&attnout, g_attnout);
    cudaGetSymbolAddress((void**)&h2,      g_h2);
    cudaGetSymbolAddress((void**)&gate,    g_gate);
    cudaGetSymbolAddress((void**)&up,      g_up);
    cudaGetSymbolAddress((void**)&ffnout,  g_ffnout);

    __half *h_h, *h_l, *attn_h, *attn_l, *ffnin_h, *ffnin_l, *gact_h;
    __half *pwq, *pwk, *pwv, *pwo, *pwg, *pwu, *pwd;
    cudaGetSymbolAddress((void**)&h_h, g_h_h);         cudaGetSymbolAddress((void**)&h_l, g_h_l);
    cudaGetSymbolAddress((void**)&attn_h, g_attn_h);   cudaGetSymbolAddress((void**)&attn_l, g_attn_l);
    cudaGetSymbolAddress((void**)&ffnin_h, g_ffnin_h); cudaGetSymbolAddress((void**)&ffnin_l, g_ffnin_l);
    cudaGetSymbolAddress((void**)&gact_h, g_gact_h);
    cudaGetSymbolAddress((void**)&pwq, g_wq);
    cudaGetSymbolAddress((void**)&pwk, g_wk);
    cudaGetSymbolAddress((void**)&pwv, g_wv);
    cudaGetSymbolAddress((void**)&pwo, g_wo);
    cudaGetSymbolAddress((void**)&pwg, g_wg);
    cudaGetSymbolAddress((void**)&pwu, g_wu);
    cudaGetSymbolAddress((void**)&pwd, g_wd);

    const int smem2 = 2 * 3 * PLANE_H * 2;   // 2-pass: 2 stages x 3 planes
    const int smem1 = 3 * 2 * PLANE_H * 2;   // 1-pass: 3 stages x 2 planes
    cudaFuncSetAttribute(attn_mma_kernel, cudaFuncAttributeMaxDynamicSharedMemorySize, ATTN2_SMEM);
    cudaFuncSetAttribute(gemm_mma<true>,  cudaFuncAttributeMaxDynamicSharedMemorySize, smem2);
    cudaFuncSetAttribute(gemm_mma<false>, cudaFuncAttributeMaxDynamicSharedMemorySize, smem1);

    // weight planes (fp16)
    wsplit_kernel<<<2048, 256>>>(wq, pwq, H_SIZE*H_SIZE/4);
    wsplit_kernel<<<1024, 256>>>(wk, pwk, NKV*HD*H_SIZE/4);
    wsplit_kernel<<<1024, 256>>>(wv, pwv, NKV*HD*H_SIZE/4);
    wsplit_kernel<<<2048, 256>>>(wo, pwo, H_SIZE*H_SIZE/4);
    wsplit_kernel<<<4096, 256>>>(wg, pwg, INTER_SZ*H_SIZE/4);
    wsplit_kernel<<<4096, 256>>>(wu, pwu, INTER_SZ*H_SIZE/4);
    wsplit_kernel<<<4096, 256>>>(wd, pwd, H_SIZE*INTER_SZ/4);

    // h = rmsnorm(x, w_in) -> fp16 hi/lo planes
    rmsnorm_split_kernel<<<NROWS, 256>>>(x, w_in, h_h, h_l);
    // QKV (2-pass)
    gemm_mma<true><<<dim3(H_SIZE/128, NROWS/128), 256, smem2>>>(h_h, h_l, pwq, q, NROWS, H_SIZE, H_SIZE);
    gemm_mma<true><<<dim3((NKV*HD)/128, NROWS/128), 256, smem2>>>(h_h, h_l, pwk, k, NROWS, NKV*HD, H_SIZE);
    gemm_mma<true><<<dim3((NKV*HD)/128, NROWS/128), 256, smem2>>>(h_h, h_l, pwv, v, NROWS, NKV*HD, H_SIZE);
    // RoPE
    rope_kernel<<<NROWS, 256>>>(q, NQ);
    rope_kernel<<<NROWS, 256>>>(k, NKV);
    // tensor-core attention -> fp16 planes
    attn_mma_kernel<<<dim3(SEQ/128, NQ, BATCH), 256, ATTN2_SMEM>>>(q, k, v, attn_h, attn_l);
    // WO (2-pass)
    gemm_mma<true><<<dim3(H_SIZE/128, NROWS/128), 256, smem2>>>(attn_h, attn_l, pwo, attnout, NROWS, H_SIZE, H_SIZE);
    // h2 = x + rmsnorm(attnout, w_pa)
    rmsnorm_kernel<<<NROWS, 256>>>(attnout, w_pa, x, nullptr, h2, 1);
    // ffn_in = rmsnorm(h2, w_pf) -> fp16 planes
    rmsnorm_split_kernel<<<NROWS, 256>>>(h2, w_pf, ffnin_h, ffnin_l);
    // gate/up GEMMs (1-pass fp16, 3-stage pipeline)
    gemm_mma<false><<<dim3(INTER_SZ/128, NROWS/128), 256, smem1>>>(ffnin_h, nullptr, pwg, gate, NROWS, INTER_SZ, H_SIZE);
    gemm_mma<false><<<dim3(INTER_SZ/128, NROWS/128), 256, smem1>>>(ffnin_h, nullptr, pwu, up, NROWS, INTER_SZ, H_SIZE);
    // act = gelu(gate) * up -> fp16 hi plane
    geglu_kernel<<<8192, 256>>>(gate, up, gact_h, (NROWS * INTER_SZ) / 4);
    // down projection (1-pass fp16, K = INTER, 3-stage pipeline)
    gemm_mma<false><<<dim3(H_SIZE/128, NROWS/128), 256, smem1>>>(gact_h, nullptr, pwd, ffnout, NROWS, H_SIZE, INTER_SZ);
    // out = (h2 + rmsnorm(ffnout, w_pff)) * layer_scalar
    rmsnorm_kernel<<<NROWS, 256>>>(ffnout, w_pff, h2, lsc, out, 2);
}

// round 17
// speedup vs baseline: 1.1301x; 1.0622x over previous
#include <cuda_runtime.h>
#include <cuda_fp16.h>
#include <stdint.h>
#include <math.h>

#define H_SIZE 2048
#define INTER_SZ 8192
#define NQ 16
#define NKV 8
#define HD 128
#define SEQ 2048
#define BATCH 2
#define NROWS (BATCH*SEQ)
#define WIN 1024

// ---------------- fp32 scratch ----------------
__device__ float g_q[NROWS*H_SIZE];
__device__ float g_k[NROWS*NKV*HD];
__device__ float g_v[NROWS*NKV*HD];
__device__ float g_attnout[NROWS*H_SIZE];
__device__ float g_h2[NROWS*H_SIZE];
__device__ float g_gate[NROWS*INTER_SZ];     // holds gelu(gate) after gate GEMM
__device__ float g_ffnout[NROWS*H_SIZE];

// ---------------- fp16 planes ----------------
__device__ __half g_h_h[NROWS*H_SIZE],      g_h_l[NROWS*H_SIZE];
__device__ __half g_attn_h[NROWS*H_SIZE];
__device__ __half g_ffnin_h[NROWS*H_SIZE],  g_ffnin_l[NROWS*H_SIZE];
__device__ __half g_gact_h[NROWS*INTER_SZ];
__device__ __half g_wq[H_SIZE*H_SIZE];
__device__ __half g_wk[NKV*HD*H_SIZE];
__device__ __half g_wv[NKV*HD*H_SIZE];
__device__ __half g_wo[H_SIZE*H_SIZE];
__device__ __half g_wg[INTER_SZ*H_SIZE];
__device__ __half g_wu[INTER_SZ*H_SIZE];
__device__ __half g_wd[H_SIZE*INTER_SZ];

// ---------------- helpers ----------------
__device__ __forceinline__ void split2h(float a, float b, __half* hi, __half* lo) {
    __half ha = __float2half(a), hb = __float2half(b);
    __half la = __float2half(a - __half2float(ha));
    __half lb = __float2half(b - __half2float(hb));
    *(__half2*)hi = __halves2half2(ha, hb);
    *(__half2*)lo = __halves2half2(la, lb);
}

__device__ __forceinline__ float gelu_exact(float x) {
    return 0.5f * x * (1.0f + erff(x * 0.7071067811865476f));
}

__global__ __launch_bounds__(256) void wsplit_kernel(
    const float* __restrict__ in, __half* __restrict__ out, int n4)
{
    int i = blockIdx.x * blockDim.x + threadIdx.x;
    int stride = gridDim.x * blockDim.x;
    for (; i < n4; i += stride) {
        float4 v = ((const float4*)in)[i];
        *(__half2*)(out + i*4)     = __halves2half2(__float2half(v.x), __float2half(v.y));
        *(__half2*)(out + i*4 + 2) = __halves2half2(__float2half(v.z), __float2half(v.w));
    }
}

// ---------------- RMSNorm fp32 out (mode 2: (res+norm)*scalar) ----------------
__global__ __launch_bounds__(256) void rmsnorm_kernel(
    const float* __restrict__ in, const float* __restrict__ w,
    const float* __restrict__ res, const float* __restrict__ scal,
    float* __restrict__ out, int mode)
{
    int row = blockIdx.x;
    int t = threadIdx.x;
    const float4* ip = (const float4*)(in + (size_t)row * H_SIZE);
    float4 v0 = ip[t];
    float4 v1 = ip[t + 256];
    float ss = v0.x*v0.x + v0.y*v0.y + v0.z*v0.z + v0.w*v0.w
             + v1.x*v1.x + v1.y*v1.y + v1.z*v1.z + v1.w*v1.w;
    #pragma unroll
    for (int o = 16; o; o >>= 1) ss += __shfl_xor_sync(0xffffffffu, ss, o);
    __shared__ float red[8];
    if ((t & 31) == 0) red[t >> 5] = ss;
    __syncthreads();
    float tot = red[0]+red[1]+red[2]+red[3]+red[4]+red[5]+red[6]+red[7];
    float inv = rsqrtf(tot * (1.0f / H_SIZE) + 1e-6f);

    const float4* w4 = (const float4*)w;
    float4 w0 = w4[t], w1 = w4[t + 256];
    float4 o0, o1;
    o0.x = v0.x*inv*w0.x; o0.y = v0.y*inv*w0.y; o0.z = v0.z*inv*w0.z; o0.w = v0.w*inv*w0.w;
    o1.x = v1.x*inv*w1.x; o1.y = v1.y*inv*w1.y; o1.z = v1.z*inv*w1.z; o1.w = v1.w*inv*w1.w;
    if (mode >= 1) {
        const float4* rp = (const float4*)(res + (size_t)row * H_SIZE);
        float4 r0 = rp[t], r1 = rp[t + 256];
        o0.x += r0.x; o0.y += r0.y; o0.z += r0.z; o0.w += r0.w;
        o1.x += r1.x; o1.y += r1.y; o1.z += r1.z; o1.w += r1.w;
    }
    if (mode == 2) {
        float sc = scal[0];
        o0.x *= sc; o0.y *= sc; o0.z *= sc; o0.w *= sc;
        o1.x *= sc; o1.y *= sc; o1.z *= sc; o1.w *= sc;
    }
    float4* op = (float4*)(out + (size_t)row * H_SIZE);
    op[t] = o0;
    op[t + 256] = o1;
}

// ---------------- RMSNorm -> fp16 hi/lo planes ----------------
__global__ __launch_bounds__(256) void rmsnorm_split_kernel(
    const float* __restrict__ in, const float* __restrict__ w,
    __half* __restrict__ oh, __half* __restrict__ ol)
{
    int row = blockIdx.x;
    int t = threadIdx.x;
    const float4* ip = (const float4*)(in + (size_t)row * H_SIZE);
    float4 v0 = ip[t];
    float4 v1 = ip[t + 256];
    float ss = v0.x*v0.x + v0.y*v0.y + v0.z*v0.z + v0.w*v0.w
             + v1.x*v1.x + v1.y*v1.y + v1.z*v1.z + v1.w*v1.w;
    #pragma unroll
    for (int o = 16; o; o >>= 1) ss += __shfl_xor_sync(0xffffffffu, ss, o);
    __shared__ float red[8];
    if ((t & 31) == 0) red[t >> 5] = ss;
    __syncthreads();
    float tot = red[0]+red[1]+red[2]+red[3]+red[4]+red[5]+red[6]+red[7];
    float inv = rsqrtf(tot * (1.0f / H_SIZE) + 1e-6f);

    const float4* w4 = (const float4*)w;
    float4 w0 = w4[t], w1 = w4[t + 256];
    size_t base = (size_t)row * H_SIZE;
    split2h(v0.x*inv*w0.x, v0.y*inv*w0.y, oh + base + t*4,     ol + base + t*4);
    split2h(v0.z*inv*w0.z, v0.w*inv*w0.w, oh + base + t*4 + 2, ol + base + t*4 + 2);
    split2h(v1.x*inv*w1.x, v1.y*inv*w1.y, oh + base + 1024 + t*4,     ol + base + 1024 + t*4);
    split2h(v1.z*inv*w1.z, v1.w*inv*w1.w, oh + base + 1024 + t*4 + 2, ol + base + 1024 + t*4 + 2);
}

// ---------------- Fused: h2 = x + rmsnorm(attnout,w_pa); ffnin planes = split(rmsnorm(h2,w_pf))
__global__ __launch_bounds__(256) void rmsnorm_fuse_kernel(
    const float* __restrict__ attnout, const float* __restrict__ w_pa,
    const float* __restrict__ x, const float* __restrict__ w_pf,
    float* __restrict__ h2, __half* __restrict__ oh, __half* __restrict__ ol)
{
    int row = blockIdx.x;
    int t = threadIdx.x;
    const float4* ip = (const float4*)(attnout + (size_t)row * H_SIZE);
    float4 a0 = ip[t];
    float4 a1 = ip[t + 256];
    float ss = a0.x*a0.x + a0.y*a0.y + a0.z*a0.z + a0.w*a0.w
             + a1.x*a1.x + a1.y*a1.y + a1.z*a1.z + a1.w*a1.w;
    #pragma unroll
    for (int o = 16; o; o >>= 1) ss += __shfl_xor_sync(0xffffffffu, ss, o);
    __shared__ float red1[8], red2[8];
    if ((t & 31) == 0) red1[t >> 5] = ss;
    __syncthreads();
    float tot = red1[0]+red1[1]+red1[2]+red1[3]+red1[4]+red1[5]+red1[6]+red1[7];
    float inv1 = rsqrtf(tot * (1.0f / H_SIZE) + 1e-6f);

    const float4* wa4 = (const float4*)w_pa;
    float4 wa0 = wa4[t], wa1 = wa4[t + 256];
    const float4* xp = (const float4*)(x + (size_t)row * H_SIZE);
    float4 x0 = xp[t], x1 = xp[t + 256];
    float4 h0, h1;
    h0.x = x0.x + a0.x*inv1*wa0.x; h0.y = x0.y + a0.y*inv1*wa0.y;
    h0.z = x0.z + a0.z*inv1*wa0.z; h0.w = x0.w + a0.w*inv1*wa0.w;
    h1.x = x1.x + a1.x*inv1*wa1.x; h1.y = x1.y + a1.y*inv1*wa1.y;
    h1.z = x1.z + a1.z*inv1*wa1.z; h1.w = x1.w + a1.w*inv1*wa1.w;
    float4* hp = (float4*)(h2 + (size_t)row * H_SIZE);
    hp[t] = h0;
    hp[t + 256] = h1;

    float ss2 = h0.x*h0.x + h0.y*h0.y + h0.z*h0.z + h0.w*h0.w
              + h1.x*h1.x + h1.y*h1.y + h1.z*h1.z + h1.w*h1.w;
    #pragma unroll
    for (int o = 16; o; o >>= 1) ss2 += __shfl_xor_sync(0xffffffffu, ss2, o);
    if ((t & 31) == 0) red2[t >> 5] = ss2;
    __syncthreads();
    float tot2 = red2[0]+red2[1]+red2[2]+red2[3]+red2[4]+red2[5]+red2[6]+red2[7];
    float inv2 = rsqrtf(tot2 * (1.0f / H_SIZE) + 1e-6f);

    const float4* wf4 = (const float4*)w_pf;
    float4 wf0 = wf4[t], wf1 = wf4[t + 256];
    size_t base = (size_t)row * H_SIZE;
    split2h(h0.x*inv2*wf0.x, h0.y*inv2*wf0.y, oh + base + t*4,     ol + base + t*4);
    split2h(h0.z*inv2*wf0.z, h0.w*inv2*wf0.w, oh + base + t*4 + 2, ol + base + t*4 + 2);
    split2h(h1.x*inv2*wf1.x, h1.y*inv2*wf1.y, oh + base + 1024 + t*4,     ol + base + 1024 + t*4);
    split2h(h1.z*inv2*wf1.z, h1.w*inv2*wf1.w, oh + base + 1024 + t*4 + 2, ol + base + 1024 + t*4 + 2);
}

// ---------------- MMA helpers ----------------
__device__ __forceinline__ void mma_fp16(float* c, const uint32_t* a, const uint32_t* b) {
    asm volatile(
        "mma.sync.aligned.m16n8k16.row.col.f32.f16.f16.f32 "
        "{%0,%1,%2,%3}, {%4,%5,%6,%7}, {%8,%9}, {%0,%1,%2,%3};\n"
        : "+f"(c[0]), "+f"(c[1]), "+f"(c[2]), "+f"(c[3])
        : "r"(a[0]), "r"(a[1]), "r"(a[2]), "r"(a[3]), "r"(b[0]), "r"(b[1]));
}

__device__ __forceinline__ void ldsm_x4(uint32_t* r, uint32_t addr) {
    asm volatile("ldmatrix.sync.aligned.m8n8.x4.shared.b16 {%0,%1,%2,%3}, [%4];"
        : "=r"(r[0]), "=r"(r[1]), "=r"(r[2]), "=r"(r[3]) : "r"(addr));
}

__device__ __forceinline__ void ldsm_x4_t(uint32_t* r, uint32_t addr) {
    asm volatile("ldmatrix.sync.aligned.m8n8.x4.trans.shared.b16 {%0,%1,%2,%3}, [%4];"
        : "=r"(r[0]), "=r"(r[1]), "=r"(r[2]), "=r"(r[3]) : "r"(addr));
}

__device__ __forceinline__ void cp16(uint32_t dst, const void* src) {
    asm volatile("cp.async.cg.shared.global [%0], [%1], 16;\n" :: "r"(dst), "l"(src));
}

// ---------------- Tensor-core GEMM (R13 geometry): block 128x128, warp tile 32x64 --------
// 2 CTAs/SM, 2-stage cp.async. TWOPASS: 3 planes. EPI: 0=store fp32, 1=store gelu fp32,
// 2=read Gin, store fp16(acc*Gin) to Hout.

#define LDSK 40
#define PLANE_H (128*LDSK)

template<bool TWOPASS, int EPI>
__global__ __launch_bounds__(256, 2) void gemm_mma(
    const __half* __restrict__ Agh, const __half* __restrict__ Agl,
    const __half* __restrict__ Bgh,
    float* __restrict__ C, const float* __restrict__ Gin,
    __half* __restrict__ Hout, int M, int N, int K)
{
    extern __shared__ __align__(16) __half smp[];
    const int NPL = TWOPASS ? 3 : 2;
    const int STAGE_HH = NPL * PLANE_H;

    const int tid  = threadIdx.x;
    const int warp = tid >> 5, lane = tid & 31;
    const int wm = warp >> 1, wn = warp & 1;
    const int rowA = blockIdx.y * 128;
    const int colB = blockIdx.x * 128;

    const uint32_t smb = (uint32_t)__cvta_generic_to_shared(smp);
    const uint32_t a_off = (uint32_t)(((wm*32 + (lane & 15)) * LDSK + ((lane >> 4) * 8)) * 2);
    const uint32_t b_off = (uint32_t)(((wn*64 + ((lane >> 4) * 8) + (lane & 7)) * LDSK
                                       + (((lane >> 3) & 1) * 8)) * 2);

    float acc[2][8][4];
    #pragma unroll
    for (int i = 0; i < 2; i++)
        #pragma unroll
        for (int j = 0; j < 8; j++)
            #pragma unroll
            for (int q = 0; q < 4; q++) acc[i][j][q] = 0.f;

    #define CP_STAGE(s, k0)                                                        \
    {                                                                              \
        _Pragma("unroll")                                                          \
        for (int i = 0; i < 2*NPL; i++) {                                          \
            int cidx = tid + 256 * i;                                              \
            int plane = cidx >> 9;                                                 \
            int cc = cidx & 511;                                                   \
            int row = cc >> 2;                                                     \
            int ch = cc & 3;                                                       \
            const __half* src =                                                    \
                (plane == 0) ? Agh + (size_t)(rowA + row) * K :                    \
                (plane == 1) ? Bgh + (size_t)(colB + row) * K :                    \
                               Agl + (size_t)(rowA + row) * K;                     \
            uint32_t dst = smb +                                                   \
                (uint32_t)(((s) * STAGE_HH + plane * PLANE_H + row * LDSK + ch * 8) * 2); \
            cp16(dst, src + (k0) + ch * 8);                                        \
        }                                                                          \
        asm volatile("cp.async.commit_group;\n" ::: "memory");                     \
    }

    const int NC = K >> 5;
    CP_STAGE(0, 0);
    for (int c = 0; c < NC; c++) {
        int s = c & 1;
        if (c + 1 < NC) {
            CP_STAGE(s ^ 1, (c + 1) * 32);
            asm volatile("cp.async.wait_group 1;\n" ::: "memory");
        } else {
            asm volatile("cp.async.wait_group 0;\n" ::: "memory");
        }
        __syncthreads();

        const uint32_t ah_b = smb + (uint32_t)((s * STAGE_HH) * 2);
        const uint32_t bh_b = ah_b + (uint32_t)(PLANE_H * 2);
        const uint32_t al_b = bh_b + (uint32_t)(PLANE_H * 2);

        #pragma unroll
        for (int kk = 0; kk < 32; kk += 16) {
            const uint32_t kko = kk * 2;
            uint32_t fa[2][4];
            uint32_t fb[4][4];
            #pragma unroll
            for (int tm = 0; tm < 2; tm++)
                ldsm_x4(fa[tm], ah_b + a_off + (uint32_t)(tm * 16 * LDSK * 2) + kko);
            #pragma unroll
            for (int p = 0; p < 4; p++)
                ldsm_x4(fb[p], bh_b + b_off + (uint32_t)(p * 16 * LDSK * 2) + kko);
            #pragma unroll
            for (int tm = 0; tm < 2; tm++)
                #pragma unroll
                for (int tn = 0; tn < 8; tn++)
                    mma_fp16(acc[tm][tn], fa[tm], &fb[tn >> 1][(tn & 1) * 2]);
            if (TWOPASS) {
                uint32_t fal[2][4];
                #pragma unroll
                for (int tm = 0; tm < 2; tm++)
                    ldsm_x4(fal[tm], al_b + a_off + (uint32_t)(tm * 16 * LDSK * 2) + kko);
                #pragma unroll
                for (int tm = 0; tm < 2; tm++)
                    #pragma unroll
                    for (int tn = 0; tn < 8; tn++)
                        mma_fp16(acc[tm][tn], fal[tm], &fb[tn >> 1][(tn & 1) * 2]);
            }
        }
        __syncthreads();
    }

    const int g4 = lane >> 2, t4 = lane & 3;
    #pragma unroll
    for (int tm = 0; tm < 2; tm++) {
        #pragma unroll
        for (int tn = 0; tn < 8; tn++) {
            int row = blockIdx.y*128 + wm*32 + tm*16 + g4;
            int col = blockIdx.x*128 + wn*64 + tn*8 + 2*t4;
            if (EPI == 0) {
                float2 c0 = {acc[tm][tn][0], acc[tm][tn][1]};
                float2 c1 = {acc[tm][tn][2], acc[tm][tn][3]};
                *(float2*)(C + (size_t)row * N + col)       = c0;
                *(float2*)(C + (size_t)(row + 8) * N + col) = c1;
            } else if (EPI == 1) {
                float2 c0 = {gelu_exact(acc[tm][tn][0]), gelu_exact(acc[tm][tn][1])};
                float2 c1 = {gelu_exact(acc[tm][tn][2]), gelu_exact(acc[tm][tn][3])};
                *(float2*)(C + (size_t)row * N + col)       = c0;
                *(float2*)(C + (size_t)(row + 8) * N + col) = c1;
            } else {
                float2 ga = *(const float2*)(Gin + (size_t)row * N + col);
                float2 gb = *(const float2*)(Gin + (size_t)(row + 8) * N + col);
                __half2 h0 = __halves2half2(__float2half(ga.x * acc[tm][tn][0]),
                                            __float2half(ga.y * acc[tm][tn][1]));
                __half2 h1 = __halves2half2(__float2half(gb.x * acc[tm][tn][2]),
                                            __float2half(gb.y * acc[tm][tn][3]));
                *(__half2*)(Hout + (size_t)row * N + col)       = h0;
                *(__half2*)(Hout + (size_t)(row + 8) * N + col) = h1;
            }
        }
    }
}

// ---------------- RoPE ----------------
__global__ __launch_bounds__(256) void rope_kernel(float* __restrict__ buf, int nheads)
{
    int row = blockIdx.x;
    int s = row & (SEQ - 1);
    float* base = buf + (size_t)row * nheads * HD;
    for (int idx = threadIdx.x; idx < nheads * 64; idx += blockDim.x) {
        int hh = idx >> 6;
        int d = idx & 63;
        float inv = expf(-((float)d * (1.0f / 64.0f)) * 9.210340371976184f);
        float fr = (float)s * inv;
        float sn = sinf(fr), cs = cosf(fr);
        float* p = base + hh * HD + d;
        float x1 = p[0], x2 = p[64];
        p[0]  = x1 * cs - x2 * sn;
        p[64] = x2 * cs + x1 * sn;
    }
}

// ---------------- Tensor-core sliding-window GQA flash attention (hi-plane out) ----------
#define ASTR 136
#define ATTN2_SMEM ((128*ASTR*2 + 32*ASTR*4) * 2)

__global__ __launch_bounds__(256) void attn_mma_kernel(
    const float* __restrict__ Q, const float* __restrict__ K,
    const float* __restrict__ V, __half* __restrict__ Oh)
{
    extern __shared__ __align__(16) __half asmem[];
    __half* Qh = asmem;
    __half* Ql = Qh + 128*ASTR;
    __half* Kh = Ql + 128*ASTR;
    __half* Kl = Kh + 32*ASTR;
    __half* Vh = Kl + 32*ASTR;
    __half* Vl = Vh + 32*ASTR;

    const int i0 = blockIdx.x * 128;
    const int h  = blockIdx.y;
    const int b  = blockIdx.z;
    const int hk = h >> 1;
    const int tid = threadIdx.x;
    const int w = tid >> 5, lane = tid & 31;
    const int g = lane >> 2, t = lane & 3;
    const float scale = 0.08838834764831845f;

    const uint32_t qh_b = (uint32_t)__cvta_generic_to_shared(Qh);
    const uint32_t ql_b = (uint32_t)__cvta_generic_to_shared(Ql);
    const uint32_t kh_b = (uint32_t)__cvta_generic_to_shared(Kh);
    const uint32_t kl_b = (uint32_t)__cvta_generic_to_shared(Kl);
    const uint32_t vh_b = (uint32_t)__cvta_generic_to_shared(Vh);
    const uint32_t vl_b = (uint32_t)__cvta_generic_to_shared(Vl);

    const uint32_t a_off  = (uint32_t)(((w*16 + (lane & 15)) * ASTR + ((lane >> 4) * 8)) * 2);
    const uint32_t kb_off = (uint32_t)((((lane >> 4) * 8 + (lane & 7)) * ASTR
                                        + ((lane >> 3) & 1) * 8) * 2);
    const uint32_t vt_off = (uint32_t)((((lane & 7) + 8 * ((lane >> 3) & 1)) * ASTR
                                        + 8 * (lane >> 4)) * 2);

    #pragma unroll
    for (int it = 0; it < 16; it++) {
        int idx = tid + 256 * it;
        int row = idx >> 5, d4 = idx & 31;
        float4 qv = *(const float4*)(Q + (size_t)(b * SEQ + i0 + row) * H_SIZE + h * HD + d4 * 4);
        int off = row * ASTR + d4 * 4;
        split2h(qv.x * scale, qv.y * scale, Qh + off,     Ql + off);
        split2h(qv.z * scale, qv.w * scale, Qh + off + 2, Ql + off + 2);
    }

    float accO[16][4];
    #pragma unroll
    for (int i = 0; i < 16; i++)
        #pragma unroll
        for (int q = 0; q < 4; q++) accO[i][q] = 0.f;
    float m0 = -1e30f, m1 = -1e30f, l0 = 0.f, l1 = 0.f;

    int jstart = i0 - (WIN - 1);
    if (jstart < 0) jstart = 0;
    jstart &= ~31;
    const int r0 = i0 + w*16 + g;
    const int r1 = r0 + 8;

    for (int j0 = jstart; j0 < i0 + 128; j0 += 32) {
        __syncthreads();
        #pragma unroll
        for (int it = 0; it < 4; it++) {
            int idx = tid + 256 * it;
            int row = idx >> 5, d4 = idx & 31;
            size_t goff = (size_t)(b * SEQ + j0 + row) * (NKV * HD) + hk * HD + d4 * 4;
            float4 kv = *(const float4*)(K + goff);
            float4 vv = *(const float4*)(V + goff);
            int off = row * ASTR + d4 * 4;
            split2h(kv.x, kv.y, Kh + off,     Kl + off);
            split2h(kv.z, kv.w, Kh + off + 2, Kl + off + 2);
            split2h(vv.x, vv.y, Vh + off,     Vl + off);
            split2h(vv.z, vv.w, Vh + off + 2, Vl + off + 2);
        }
        __syncthreads();

        float accS[4][4];
        #pragma unroll
        for (int nt = 0; nt < 4; nt++)
            #pragma unroll
            for (int q = 0; q < 4; q++) accS[nt][q] = 0.f;

        #pragma unroll
        for (int ks = 0; ks < 8; ks++) {
            const uint32_t kko = (uint32_t)(ks * 32);
            uint32_t fa[4], fal[4], fb[2][4], fbl[2][4];
            ldsm_x4(fa,  qh_b + a_off + kko);
            ldsm_x4(fal, ql_b + a_off + kko);
            ldsm_x4(fb[0],  kh_b + kb_off + kko);
            ldsm_x4(fb[1],  kh_b + kb_off + (uint32_t)(16 * ASTR * 2) + kko);
            ldsm_x4(fbl[0], kl_b + kb_off + kko);
            ldsm_x4(fbl[1], kl_b + kb_off + (uint32_t)(16 * ASTR * 2) + kko);
            #pragma unroll
            for (int nt = 0; nt < 4; nt++) {
                mma_fp16(accS[nt], fa,  &fb[nt >> 1][(nt & 1) * 2]);
                mma_fp16(accS[nt], fal, &fb[nt >> 1][(nt & 1) * 2]);
                mma_fp16(accS[nt], fa,  &fbl[nt >> 1][(nt & 1) * 2]);
            }
        }

        #pragma unroll
        for (int nt = 0; nt < 4; nt++) {
            int jc0 = j0 + nt * 8 + 2 * t;
            int jc1 = jc0 + 1;
            accS[nt][0] = (jc0 <= r0 && r0 - jc0 < WIN) ? accS[nt][0] : -1e30f;
            accS[nt][1] = (jc1 <= r0 && r0 - jc1 < WIN) ? accS[nt][1] : -1e30f;
            accS[nt][2] = (jc0 <= r1 && r1 - jc0 < WIN) ? accS[nt][2] : -1e30f;
            accS[nt][3] = (jc1 <= r1 && r1 - jc1 < WIN) ? accS[nt][3] : -1e30f;
        }

        float mt0 = m0, mt1 = m1;
        #pragma unroll
        for (int nt = 0; nt < 4; nt++) {
            mt0 = fmaxf(mt0, fmaxf(accS[nt][0], accS[nt][1]));
            mt1 = fmaxf(mt1, fmaxf(accS[nt][2], accS[nt][3]));
        }
        mt0 = fmaxf(mt0, __shfl_xor_sync(0xffffffffu, mt0, 1));
        mt0 = fmaxf(mt0, __shfl_xor_sync(0xffffffffu, mt0, 2));
        mt1 = fmaxf(mt1, __shfl_xor_sync(0xffffffffu, mt1, 1));
        mt1 = fmaxf(mt1, __shfl_xor_sync(0xffffffffu, mt1, 2));
        float alpha0 = __expf(m0 - mt0);
        float alpha1 = __expf(m1 - mt1);
        m0 = mt0; m1 = mt1;

        float p[4][4];
        float ps0 = 0.f, ps1 = 0.f;
        #pragma unroll
        for (int nt = 0; nt < 4; nt++) {
            p[nt][0] = __expf(accS[nt][0] - mt0);
            p[nt][1] = __expf(accS[nt][1] - mt0);
            p[nt][2] = __expf(accS[nt][2] - mt1);
            p[nt][3] = __expf(accS[nt][3] - mt1);
            ps0 += p[nt][0] + p[nt][1];
            ps1 += p[nt][2] + p[nt][3];
        }
        ps0 += __shfl_xor_sync(0xffffffffu, ps0, 1);
        ps0 += __shfl_xor_sync(0xffffffffu, ps0, 2);
        ps1 += __shfl_xor_sync(0xffffffffu, ps1, 1);
        ps1 += __shfl_xor_sync(0xffffffffu, ps1, 2);
        l0 = l0 * alpha0 + ps0;
        l1 = l1 * alpha1 + ps1;

        #pragma unroll
        for (int i = 0; i < 16; i++) {
            accO[i][0] *= alpha0; accO[i][1] *= alpha0;
            accO[i][2] *= alpha1; accO[i][3] *= alpha1;
        }

        uint32_t ph[2][4], pl[2][4];
        #pragma unroll
        for (int kb = 0; kb < 2; kb++) {
            #pragma unroll
            for (int q = 0; q < 4; q++) {
                int nt = 2*kb + (q >> 1);
                int e0 = (q & 1) * 2;
                float v0 = p[nt][e0], v1 = p[nt][e0 + 1];
                __half h0 = __float2half(v0), h1 = __float2half(v1);
                __half lo0 = __float2half(v0 - __half2float(h0));
                __half lo1 = __float2half(v1 - __half2float(h1));
                int ridx = (q >> 1) * 2 + (q & 1);
                __half2 hh = __halves2half2(h0, h1);
                __half2 ll = __halves2half2(lo0, lo1);
                ph[kb][ridx] = *(uint32_t*)&hh;
                pl[kb][ridx] = *(uint32_t*)&ll;
            }
        }

        #pragma unroll
        for (int kb = 0; kb < 2; kb++) {
            #pragma unroll
            for (int dg = 0; dg < 8; dg++) {
                uint32_t vb[4], vbl[4];
                uint32_t voff = vt_off + (uint32_t)((kb * 16 * ASTR + dg * 16) * 2);
                ldsm_x4_t(vb,  vh_b + voff);
                ldsm_x4_t(vbl, vl_b + voff);
                mma_fp16(accO[2*dg],     ph[kb], &vb[0]);
                mma_fp16(accO[2*dg],     pl[kb], &vb[0]);
                mma_fp16(accO[2*dg],     ph[kb], &vbl[0]);
                mma_fp16(accO[2*dg + 1], ph[kb], &vb[2]);
                mma_fp16(accO[2*dg + 1], pl[kb], &vb[2]);
                mma_fp16(accO[2*dg + 1], ph[kb], &vbl[2]);
            }
        }
    }

    float li0 = 1.0f / l0, li1 = 1.0f / l1;
    size_t ob0 = (size_t)(b * SEQ + i0 + w*16 + g) * H_SIZE + h * HD;
    size_t ob1 = ob0 + (size_t)8 * H_SIZE;
    #pragma unroll
    for (int nt = 0; nt < 16; nt++) {
        int dim = nt * 8 + 2 * t;
        *(__half2*)(Oh + ob0 + dim) = __halves2half2(
            __float2half(accO[nt][0] * li0), __float2half(accO[nt][1] * li0));
        *(__half2*)(Oh + ob1 + dim) = __halves2half2(
            __float2half(accO[nt][2] * li1), __float2half(accO[nt][3] * li1));
    }
}

// ---------------- launch ----------------
extern "C" void kernel_launch(void* const* d_in, const int* in_sizes, int n_in,
                              void* d_out, int out_size)
{
    const float* x    = (const float*)d_in[0];
    const float* wq   = (const float*)d_in[1];
    const float* wk   = (const float*)d_in[2];
    const float* wv   = (const float*)d_in[3];
    const float* wo   = (const float*)d_in[4];
    const float* w_in = (const float*)d_in[5];
    const float* w_pa = (const float*)d_in[6];
    const float* w_pf = (const float*)d_in[7];
    const float* w_pff= (const float*)d_in[8];
    const float* wg   = (const float*)d_in[9];
    const float* wu   = (const float*)d_in[10];
    const float* wd   = (const float*)d_in[11];
    const float* lsc  = (const float*)d_in[12];
    float* out = (float*)d_out;

    float *q, *k, *v, *attnout, *h2, *gate, *ffnout;
    cudaGetSymbolAddress((void**)&q,       g_q);
    cudaGetSymbolAddress((void**)&k,       g_k);
    cudaGetSymbolAddress((void**)&v,       g_v);
    cudaGetSymbolAddress((void**)&attnout, g_attnout);
    cudaGetSymbolAddress((void**)&h2,      g_h2);
    cudaGetSymbolAddress((void**)&gate,    g_gate);
    cudaGetSymbolAddress((void**)&ffnout,  g_ffnout);

    __half *h_h, *h_l, *attn_h, *ffnin_h, *ffnin_l, *gact_h;
    __half *pwq, *pwk, *pwv, *pwo, *pwg, *pwu, *pwd;
    cudaGetSymbolAddress((void**)&h_h, g_h_h);         cudaGetSymbolAddress((void**)&h_l, g_h_l);
    cudaGetSymbolAddress((void**)&attn_h, g_attn_h);
    cudaGetSymbolAddress((void**)&ffnin_h, g_ffnin_h); cudaGetSymbolAddress((void**)&ffnin_l, g_ffnin_l);
    cudaGetSymbolAddress((void**)&gact_h, g_gact_h);
    cudaGetSymbolAddress((void**)&pwq, g_wq);
    cudaGetSymbolAddress((void**)&pwk, g_wk);
    cudaGetSymbolAddress((void**)&pwv, g_wv);
    cudaGetSymbolAddress((void**)&pwo, g_wo);
    cudaGetSymbolAddress((void**)&pwg, g_wg);
    cudaGetSymbolAddress((void**)&pwu, g_wu);
    cudaGetSymbolAddress((void**)&pwd, g_wd);

    const int smem2 = 2 * 3 * PLANE_H * 2;   // 2-pass: 2 stages x 3 planes
    const int smem1 = 2 * 2 * PLANE_H * 2;   // 1-pass: 2 stages x 2 planes
    cudaFuncSetAttribute(attn_mma_kernel, cudaFuncAttributeMaxDynamicSharedMemorySize, ATTN2_SMEM);
    cudaFuncSetAttribute(gemm_mma<true,0>,  cudaFuncAttributeMaxDynamicSharedMemorySize, smem2);
    cudaFuncSetAttribute(gemm_mma<false,0>, cudaFuncAttributeMaxDynamicSharedMemorySize, smem1);
    cudaFuncSetAttribute(gemm_mma<false,1>, cudaFuncAttributeMaxDynamicSharedMemorySize, smem1);
    cudaFuncSetAttribute(gemm_mma<false,2>, cudaFuncAttributeMaxDynamicSharedMemorySize, smem1);

    // weight planes (fp16)
    wsplit_kernel<<<2048, 256>>>(wq, pwq, H_SIZE*H_SIZE/4);
    wsplit_kernel<<<1024, 256>>>(wk, pwk, NKV*HD*H_SIZE/4);
    wsplit_kernel<<<1024, 256>>>(wv, pwv, NKV*HD*H_SIZE/4);
    wsplit_kernel<<<2048, 256>>>(wo, pwo, H_SIZE*H_SIZE/4);
    wsplit_kernel<<<4096, 256>>>(wg, pwg, INTER_SZ*H_SIZE/4);
    wsplit_kernel<<<4096, 256>>>(wu, pwu, INTER_SZ*H_SIZE/4);
    wsplit_kernel<<<4096, 256>>>(wd, pwd, H_SIZE*INTER_SZ/4);

    // h = rmsnorm(x, w_in) -> fp16 hi/lo planes
    rmsnorm_split_kernel<<<NROWS, 256>>>(x, w_in, h_h, h_l);
    // QKV (2-pass)
    gemm_mma<true,0><<<dim3(H_SIZE/128, NROWS/128), 256, smem2>>>(h_h, h_l, pwq, q, nullptr, nullptr, NROWS, H_SIZE, H_SIZE);
    gemm_mma<true,0><<<dim3((NKV*HD)/128, NROWS/128), 256, smem2>>>(h_h, h_l, pwk, k, nullptr, nullptr, NROWS, NKV*HD, H_SIZE);
    gemm_mma<true,0><<<dim3((NKV*HD)/128, NROWS/128), 256, smem2>>>(h_h, h_l, pwv, v, nullptr, nullptr, NROWS, NKV*HD, H_SIZE);
    // RoPE
    rope_kernel<<<NROWS, 256>>>(q, NQ);
    rope_kernel<<<NROWS, 256>>>(k, NKV);
    // tensor-core attention -> fp16 hi plane
    attn_mma_kernel<<<dim3(SEQ/128, NQ, BATCH), 256, ATTN2_SMEM>>>(q, k, v, attn_h);
    // WO (1-pass)
    gemm_mma<false,0><<<dim3(H_SIZE/128, NROWS/128), 256, smem1>>>(attn_h, nullptr, pwo, attnout, nullptr, nullptr, NROWS, H_SIZE, H_SIZE);
    // fused: h2 = x + rmsnorm(attnout); ffnin planes = split(rmsnorm(h2))
    rmsnorm_fuse_kernel<<<NROWS, 256>>>(attnout, w_pa, x, w_pf, h2, ffnin_h, ffnin_l);
    // gate GEMM (1-pass, gelu epilogue -> fp32)
    gemm_mma<false,1><<<dim3(INTER_SZ/128, NROWS/128), 256, smem1>>>(ffnin_h, nullptr, pwg, gate, nullptr, nullptr, NROWS, INTER_SZ, H_SIZE);
    // up GEMM (1-pass, multiply-by-gelu(gate) epilogue -> fp16 gact)
    gemm_mma<false,2><<<dim3(INTER_SZ/128, NROWS/128), 256, smem1>>>(ffnin_h, nullptr, pwu, nullptr, gate, gact_h, NROWS, INTER_SZ, H_SIZE);
    // down projection (1-pass, K = INTER)
    gemm_mma<false,0><<<dim3(H_SIZE/128, NROWS/128), 256, smem1>>>(gact_h, nullptr, pwd, ffnout, nullptr, nullptr, NROWS, H_SIZE, INTER_SZ);
    // out = (h2 + rmsnorm(ffnout, w_pff)) * layer_scalar
    rmsnorm_kernel<<<NROWS, 256>>>(ffnout, w_pff, h2, lsc, out, 2);
}